// round 15
// baseline (speedup 1.0000x reference)
#include <cuda_runtime.h>
#include <cuda_bf16.h>
#include <cuda_fp8.h>
#include <cstdint>
#include <math_constants.h>

// ---------------- problem constants ----------------
#define Bq 8
#define Nq 2048
#define Dq 512
#define Hq 512
#define ROWS (Bq * Nq)          // 16384

// ---------------- scratch (device globals) ----------------
__device__ uint8_t g_x8[(size_t)ROWS * Dq];              // X in fp8
__device__ uint8_t g_y8[(size_t)ROWS * Dq];              // y = X@W'' fp8
__device__ uint8_t g_u8T[(size_t)Dq * ROWS];             // u^T = (X@W')^T fp8
__device__ uint8_t g_e8[(size_t)Bq * Nq * Nq];           // exp(scores)*8 fp8
__device__ float g_rs[(size_t)ROWS];                     // row sums of 8*exp
__device__ __nv_bfloat16 g_wb[(size_t)4 * Dq * Hq];      // Wq_b, Wk_b, Wv_b, WoT_b
__device__ float g_wpf[(size_t)2 * Dq * Dq];             // f32 accum for W products
__device__ uint8_t g_wpp8[(size_t)Dq * Dq];              // (W''^T)*16 fp8
__device__ uint8_t g_wp8[(size_t)Dq * Dq];               // (W'^T)*16 fp8
__device__ float g_g1[Dq];                               // Wk @ bq
__device__ float g_c2s[(size_t)ROWS];                    // (X @ g1)/sqrt(H)
__device__ float g_bias2[Dq];                            // bo + bv@Wo
__device__ float g_tmp[(size_t)ROWS * Dq];               // pre-LN fp32 (split-K accum)

// ---------------- helpers ----------------
__device__ __forceinline__ uint32_t smem_u32(const void* p) {
    uint32_t a;
    asm("{ .reg .u64 t; cvta.to.shared.u64 t, %1; cvt.u32.u64 %0, t; }" : "=r"(a) : "l"(p));
    return a;
}
#define LDSM_X4(r0, r1, r2, r3, addr) \
    asm volatile("ldmatrix.sync.aligned.m8n8.x4.shared.b16 {%0,%1,%2,%3}, [%4];" \
        : "=r"(r0), "=r"(r1), "=r"(r2), "=r"(r3) : "r"(addr))
#define CP_ASYNC16(dst, src) \
    asm volatile("cp.async.cg.shared.global [%0], [%1], 16;" :: "r"(dst), "l"(src))
#define CP_COMMIT() asm volatile("cp.async.commit_group;" ::: "memory")
#define CP_WAIT(n)  asm volatile("cp.async.wait_group %0;" :: "n"(n) : "memory")

__device__ __forceinline__ void mma_bf16(float* d, const uint32_t* a,
                                         uint32_t b0, uint32_t b1) {
    asm volatile(
        "mma.sync.aligned.m16n8k16.row.col.f32.bf16.bf16.f32 "
        "{%0,%1,%2,%3}, {%4,%5,%6,%7}, {%8,%9}, {%0,%1,%2,%3};"
        : "+f"(d[0]), "+f"(d[1]), "+f"(d[2]), "+f"(d[3])
        : "r"(a[0]), "r"(a[1]), "r"(a[2]), "r"(a[3]), "r"(b0), "r"(b1));
}
__device__ __forceinline__ void mma_fp8(float* d, const uint32_t* a,
                                        uint32_t b0, uint32_t b1) {
    asm volatile(
        "mma.sync.aligned.m16n8k32.row.col.f32.e4m3.e4m3.f32 "
        "{%0,%1,%2,%3}, {%4,%5,%6,%7}, {%8,%9}, {%0,%1,%2,%3};"
        : "+f"(d[0]), "+f"(d[1]), "+f"(d[2]), "+f"(d[3])
        : "r"(a[0]), "r"(a[1]), "r"(a[2]), "r"(a[3]), "r"(b0), "r"(b1));
}
__device__ __forceinline__ uint16_t f2_to_fp8x2(float x, float y) {
    return (uint16_t)__nv_cvt_float2_to_fp8x2(make_float2(x, y),
                                              __NV_SATFINITE, __NV_E4M3);
}

// ---------------- shared tiling constants ----------------
#define RPAD_B 80
#define HALF_B (128 * RPAD_B)                     // 10240
#define STAGE_T (2 * HALF_B)                      // 20480
#define NSTAGE 4
#define SMEM_TOTAL (NSTAGE * STAGE_T)             // 81920 (dynamic)

// ===================== split-K bf16 weight products =====================
// grid (4,4,8): z = prod*4 + kslice. outf[prod] += A @ B^T over K chunk of 128.
__global__ __launch_bounds__(256) void mma_gemm_w2s(
    const __nv_bfloat16* __restrict__ A0, const __nv_bfloat16* __restrict__ B0,
    const __nv_bfloat16* __restrict__ A1, const __nv_bfloat16* __restrict__ B1,
    float* __restrict__ outf)
{
    extern __shared__ char smem[];
    const uint32_t sb = smem_u32(smem);
    const int tid = threadIdx.x;
    const int wid = tid >> 5;
    const int l   = tid & 31;
    const int wm  = wid & 1;
    const int wn  = wid >> 1;
    const int prod = blockIdx.z >> 2;
    const int ks   = blockIdx.z & 3;
    const int row0 = blockIdx.y * 128;
    const int col0 = blockIdx.x * 128;

    const __nv_bfloat16* A = (prod == 0) ? A0 : A1;
    const __nv_bfloat16* B = (prod == 0) ? B0 : B1;
    float* C = outf + (size_t)prod * Dq * Dq;
    const int lda = Hq, ldb = Hq;
    const int k0 = ks * 128;

    A += (long long)row0 * lda;
    B += (long long)col0 * ldb;

    const int r0  = tid >> 2;
    const int c16 = tid & 3;
    const __nv_bfloat16* Ag = A + (long long)r0 * lda + c16 * 8 + k0;
    const __nv_bfloat16* Bg = B + (long long)r0 * ldb + c16 * 8 + k0;
    const uint32_t dstA = sb + (uint32_t)(r0 * RPAD_B + c16 * 16);
    const uint32_t dstB = dstA + HALF_B;

    const uint32_t a_off = sb
        + (uint32_t)((wm * 64 + (l & 15)) * RPAD_B + ((l >> 4) & 1) * 16);
    const uint32_t b_off = sb + HALF_B
        + (uint32_t)((wn * 32 + (l & 15)) * RPAD_B + ((l >> 4) & 1) * 16);

    float acc[4][4][4];
#pragma unroll
    for (int mt = 0; mt < 4; mt++)
#pragma unroll
        for (int nt = 0; nt < 4; nt++)
#pragma unroll
            for (int i = 0; i < 4; i++) acc[mt][nt][i] = 0.f;

    auto issue_stage = [&](int s) {
        const int buf = s & (NSTAGE - 1);
        const __nv_bfloat16* ap = Ag + s * 32;
        const __nv_bfloat16* bp = Bg + s * 32;
        const uint32_t da = dstA + buf * STAGE_T;
        const uint32_t db = dstB + buf * STAGE_T;
#pragma unroll
        for (int i = 0; i < 2; i++) {
            CP_ASYNC16(da + i * 64 * RPAD_B, ap + (long long)(64 * i) * lda);
            CP_ASYNC16(db + i * 64 * RPAD_B, bp + (long long)(64 * i) * ldb);
        }
    };
    auto compute_stage = [&](int buf) {
        const uint32_t ab = a_off + buf * STAGE_T;
        const uint32_t bb = b_off + buf * STAGE_T;
#pragma unroll
        for (int kb = 0; kb < 2; kb++) {
            uint32_t afr[4][4], bfr[2][4];
#pragma unroll
            for (int mt = 0; mt < 4; mt++)
                LDSM_X4(afr[mt][0], afr[mt][1], afr[mt][2], afr[mt][3],
                        ab + mt * (16 * RPAD_B) + kb * 32);
#pragma unroll
            for (int t = 0; t < 2; t++)
                LDSM_X4(bfr[t][0], bfr[t][1], bfr[t][2], bfr[t][3],
                        bb + t * (16 * RPAD_B) + kb * 32);
#pragma unroll
            for (int mt = 0; mt < 4; mt++)
#pragma unroll
                for (int nt = 0; nt < 4; nt++)
                    mma_bf16(acc[mt][nt], afr[mt],
                             bfr[nt >> 1][nt & 1], bfr[nt >> 1][2 + (nt & 1)]);
        }
    };

    const int nst = 4;                             // 128 / 32
#pragma unroll
    for (int s = 0; s < NSTAGE - 1; s++) { issue_stage(s); CP_COMMIT(); }
    for (int s = 0; s < nst; s++) {
        CP_WAIT(NSTAGE - 2);
        __syncthreads();
        if (s + NSTAGE - 1 < nst) issue_stage(s + NSTAGE - 1);
        CP_COMMIT();
        compute_stage(s & (NSTAGE - 1));
    }

    const int lr  = l >> 2;
    const int lc2 = (l & 3) * 2;
#pragma unroll
    for (int mt = 0; mt < 4; mt++) {
        const int rA = row0 + wm * 64 + mt * 16 + lr;
#pragma unroll
        for (int nt = 0; nt < 4; nt++) {
            const int cA = col0 + wn * 32 + nt * 8 + lc2;
            atomicAdd(&C[(size_t)rA * Dq + cA],       acc[mt][nt][0]);
            atomicAdd(&C[(size_t)rA * Dq + cA + 1],   acc[mt][nt][1]);
            atomicAdd(&C[(size_t)(rA + 8) * Dq + cA],     acc[mt][nt][2]);
            atomicAdd(&C[(size_t)(rA + 8) * Dq + cA + 1], acc[mt][nt][3]);
        }
    }
}

// ---------------- convert f32 W products -> fp8 x16 ----------------
__global__ __launch_bounds__(256) void cvt_wp_k(
    const float* __restrict__ wpf, uint8_t* __restrict__ wpp8,
    uint8_t* __restrict__ wp8)
{
    const int prod = blockIdx.y;
    const size_t i = ((size_t)blockIdx.x * 256 + threadIdx.x) * 4;
    float4 v = *(const float4*)(wpf + (size_t)prod * Dq * Dq + i);
    uint16_t w0 = f2_to_fp8x2(v.x * 16.f, v.y * 16.f);
    uint16_t w1 = f2_to_fp8x2(v.z * 16.f, v.w * 16.f);
    uint8_t* O = prod ? wp8 : wpp8;
    *(uint32_t*)(O + i) = (uint32_t)w0 | ((uint32_t)w1 << 16);
}

// ===================== fp8 GEMM: y and u batched (z=2) =====================
__global__ __launch_bounds__(256) void mma_gemm_f8_yu(
    const uint8_t* __restrict__ x8, const uint8_t* __restrict__ wpp,
    const uint8_t* __restrict__ wp,
    uint8_t* __restrict__ y8, uint8_t* __restrict__ u8T)
{
    extern __shared__ char smem[];
    const uint32_t sb = smem_u32(smem);
    const int tid = threadIdx.x;
    const int wid = tid >> 5;
    const int l   = tid & 31;
    const int wm  = wid & 1;
    const int wn  = wid >> 1;

    const uint8_t* A;
    const uint8_t* B;
    uint8_t* C;
    int ldc, row0, col0;
    if (blockIdx.z == 0) {
        A = x8; B = wpp; C = y8; ldc = Dq;
        row0 = blockIdx.y * 128; col0 = blockIdx.x * 128;
    } else {
        A = wp; B = x8; C = u8T; ldc = ROWS;
        row0 = blockIdx.x * 128; col0 = blockIdx.y * 128;
    }
    const int lda = Dq, ldb = Dq, K = Dq;
    const float alpha = 1.f / 16.f;

    A += (long long)row0 * lda;
    B += (long long)col0 * ldb;
    const long long cbase = (long long)row0 * ldc + col0;

    const int r0  = tid >> 2;
    const int c16 = tid & 3;
    const uint8_t* Ag = A + (long long)r0 * lda + c16 * 16;
    const uint8_t* Bg = B + (long long)r0 * ldb + c16 * 16;
    const uint32_t dstA = sb + (uint32_t)(r0 * RPAD_B + c16 * 16);
    const uint32_t dstB = dstA + HALF_B;

    const uint32_t a_off = sb
        + (uint32_t)((wm * 64 + (l & 15)) * RPAD_B + ((l >> 4) & 1) * 16);
    const uint32_t b_off = sb + HALF_B
        + (uint32_t)((wn * 32 + (l & 15)) * RPAD_B + ((l >> 4) & 1) * 16);

    float acc[4][4][4];
#pragma unroll
    for (int mt = 0; mt < 4; mt++)
#pragma unroll
        for (int nt = 0; nt < 4; nt++)
#pragma unroll
            for (int i = 0; i < 4; i++) acc[mt][nt][i] = 0.f;

    auto issue_stage = [&](int s) {
        const int buf = s & (NSTAGE - 1);
        const uint8_t* ap = Ag + s * 64;
        const uint8_t* bp = Bg + s * 64;
        const uint32_t da = dstA + buf * STAGE_T;
        const uint32_t db = dstB + buf * STAGE_T;
#pragma unroll
        for (int i = 0; i < 2; i++) {
            CP_ASYNC16(da + i * 64 * RPAD_B, ap + (long long)(64 * i) * lda);
            CP_ASYNC16(db + i * 64 * RPAD_B, bp + (long long)(64 * i) * ldb);
        }
    };
    auto compute_stage = [&](int buf) {
        const uint32_t ab = a_off + buf * STAGE_T;
        const uint32_t bb = b_off + buf * STAGE_T;
#pragma unroll
        for (int kb = 0; kb < 2; kb++) {
            uint32_t afr[4][4], bfr[2][4];
#pragma unroll
            for (int mt = 0; mt < 4; mt++)
                LDSM_X4(afr[mt][0], afr[mt][1], afr[mt][2], afr[mt][3],
                        ab + mt * (16 * RPAD_B) + kb * 32);
#pragma unroll
            for (int t = 0; t < 2; t++)
                LDSM_X4(bfr[t][0], bfr[t][1], bfr[t][2], bfr[t][3],
                        bb + t * (16 * RPAD_B) + kb * 32);
#pragma unroll
            for (int mt = 0; mt < 4; mt++)
#pragma unroll
                for (int nt = 0; nt < 4; nt++)
                    mma_fp8(acc[mt][nt], afr[mt],
                            bfr[nt >> 1][nt & 1], bfr[nt >> 1][2 + (nt & 1)]);
        }
    };

    const int nst = K >> 6;
#pragma unroll
    for (int s = 0; s < NSTAGE - 1; s++) { issue_stage(s); CP_COMMIT(); }
    for (int s = 0; s < nst; s++) {
        CP_WAIT(NSTAGE - 2);
        __syncthreads();
        if (s + NSTAGE - 1 < nst) issue_stage(s + NSTAGE - 1);
        CP_COMMIT();
        compute_stage(s & (NSTAGE - 1));
    }

    const int lr  = l >> 2;
    const int lc2 = (l & 3) * 2;
#pragma unroll
    for (int mt = 0; mt < 4; mt++) {
        const int rA = wm * 64 + mt * 16 + lr;
#pragma unroll
        for (int nt = 0; nt < 4; nt++) {
            const int cA = wn * 32 + nt * 8 + lc2;
            *(uint16_t*)(C + cbase + (long long)rA * ldc + cA) =
                f2_to_fp8x2(acc[mt][nt][0] * alpha, acc[mt][nt][1] * alpha);
            *(uint16_t*)(C + cbase + (long long)(rA + 8) * ldc + cA) =
                f2_to_fp8x2(acc[mt][nt][2] * alpha, acc[mt][nt][3] * alpha);
        }
    }
}

// ===================== fp8 GEMM (scores / final) =====================
// MODE 1: C = fp8(8*exp(alpha*acc + c2[col])); rs += row sums   (scores)
//         grid (16,16,8): z = batch.
// MODE 2: split-K final: tmp += acc_ks / rs[row]. grid (4,16,32): z = bz*4+ks,
//         K=512 per slice. tmp pre-initialized to X + bias2.
template<int MODE>
__global__ __launch_bounds__(256) void mma_gemm_f8(
    const uint8_t* __restrict__ A, const uint8_t* __restrict__ B,
    void* __restrict__ Cv, float* __restrict__ rs,
    const float* __restrict__ c2,
    int K, int lda, int ldb, int ldc,
    long long sA, long long sB, long long sC, float alpha)
{
    extern __shared__ char smem[];
    const uint32_t sb = smem_u32(smem);
    const int tid = threadIdx.x;
    const int wid = tid >> 5;
    const int l   = tid & 31;
    const int wm  = wid & 1;
    const int wn  = wid >> 1;
    int bz, ks;
    if (MODE == 2) { bz = blockIdx.z >> 2; ks = blockIdx.z & 3; }
    else           { bz = blockIdx.z;      ks = 0; }
    const int row0 = blockIdx.y * 128;
    const int col0 = blockIdx.x * 128;

    A += (long long)bz * sA + (long long)row0 * lda + (long long)ks * 512;
    B += (long long)bz * sB + (long long)col0 * ldb + (long long)ks * 512;
    const long long cbase = (long long)bz * sC + (long long)row0 * ldc + col0;
    float* rsp = rs + (long long)bz * Nq + row0;
    const float* c2p = (MODE == 1) ? (c2 + (long long)bz * Nq + col0) : nullptr;

    const int r0  = tid >> 2;
    const int c16 = tid & 3;
    const uint8_t* Ag = A + (long long)r0 * lda + c16 * 16;
    const uint8_t* Bg = B + (long long)r0 * ldb + c16 * 16;
    const uint32_t dstA = sb + (uint32_t)(r0 * RPAD_B + c16 * 16);
    const uint32_t dstB = dstA + HALF_B;

    const uint32_t a_off = sb
        + (uint32_t)((wm * 64 + (l & 15)) * RPAD_B + ((l >> 4) & 1) * 16);
    const uint32_t b_off = sb + HALF_B
        + (uint32_t)((wn * 32 + (l & 15)) * RPAD_B + ((l >> 4) & 1) * 16);

    float acc[4][4][4];
#pragma unroll
    for (int mt = 0; mt < 4; mt++)
#pragma unroll
        for (int nt = 0; nt < 4; nt++)
#pragma unroll
            for (int i = 0; i < 4; i++) acc[mt][nt][i] = 0.f;

    auto issue_stage = [&](int s) {
        const int buf = s & (NSTAGE - 1);
        const uint8_t* ap = Ag + s * 64;
        const uint8_t* bp = Bg + s * 64;
        const uint32_t da = dstA + buf * STAGE_T;
        const uint32_t db = dstB + buf * STAGE_T;
#pragma unroll
        for (int i = 0; i < 2; i++) {
            CP_ASYNC16(da + i * 64 * RPAD_B, ap + (long long)(64 * i) * lda);
            CP_ASYNC16(db + i * 64 * RPAD_B, bp + (long long)(64 * i) * ldb);
        }
    };
    auto compute_stage = [&](int buf) {
        const uint32_t ab = a_off + buf * STAGE_T;
        const uint32_t bb = b_off + buf * STAGE_T;
#pragma unroll
        for (int kb = 0; kb < 2; kb++) {
            uint32_t afr[4][4], bfr[2][4];
#pragma unroll
            for (int mt = 0; mt < 4; mt++)
                LDSM_X4(afr[mt][0], afr[mt][1], afr[mt][2], afr[mt][3],
                        ab + mt * (16 * RPAD_B) + kb * 32);
#pragma unroll
            for (int t = 0; t < 2; t++)
                LDSM_X4(bfr[t][0], bfr[t][1], bfr[t][2], bfr[t][3],
                        bb + t * (16 * RPAD_B) + kb * 32);
#pragma unroll
            for (int mt = 0; mt < 4; mt++)
#pragma unroll
                for (int nt = 0; nt < 4; nt++)
                    mma_fp8(acc[mt][nt], afr[mt],
                            bfr[nt >> 1][nt & 1], bfr[nt >> 1][2 + (nt & 1)]);
        }
    };

    const int nst = K >> 6;
#pragma unroll
    for (int s = 0; s < NSTAGE - 1; s++) { issue_stage(s); CP_COMMIT(); }
    for (int s = 0; s < nst; s++) {
        CP_WAIT(NSTAGE - 2);
        __syncthreads();
        if (s + NSTAGE - 1 < nst) issue_stage(s + NSTAGE - 1);
        CP_COMMIT();
        compute_stage(s & (NSTAGE - 1));
    }

    uint8_t* C8 = (uint8_t*)Cv;
    float* Cf = (float*)Cv;
    const int lr  = l >> 2;
    const int lc2 = (l & 3) * 2;
#pragma unroll
    for (int mt = 0; mt < 4; mt++) {
        const int rA = wm * 64 + mt * 16 + lr;
        float sl = 0.f, sh = 0.f;
        float invl = 1.f, invh = 1.f;
        if (MODE == 2) { invl = 1.f / rsp[rA]; invh = 1.f / rsp[rA + 8]; }
#pragma unroll
        for (int nt = 0; nt < 4; nt++) {
            const int cA = wn * 32 + nt * 8 + lc2;
            float2 v0, v1;
            v0.x = acc[mt][nt][0] * alpha; v0.y = acc[mt][nt][1] * alpha;
            v1.x = acc[mt][nt][2] * alpha; v1.y = acc[mt][nt][3] * alpha;
            if (MODE == 1) {
                float2 cc = *(const float2*)(c2p + cA);
                v0.x = __expf(v0.x + cc.x) * 8.f;
                v0.y = __expf(v0.y + cc.y) * 8.f;
                v1.x = __expf(v1.x + cc.x) * 8.f;
                v1.y = __expf(v1.y + cc.y) * 8.f;
                sl += v0.x + v0.y;
                sh += v1.x + v1.y;
                *(uint16_t*)(C8 + cbase + (long long)rA * ldc + cA) =
                    f2_to_fp8x2(v0.x, v0.y);
                *(uint16_t*)(C8 + cbase + (long long)(rA + 8) * ldc + cA) =
                    f2_to_fp8x2(v1.x, v1.y);
            } else {
                float* d0 = Cf + cbase + (long long)rA * ldc + cA;
                float* d1 = Cf + cbase + (long long)(rA + 8) * ldc + cA;
                atomicAdd(d0,     v0.x * invl);
                atomicAdd(d0 + 1, v0.y * invl);
                atomicAdd(d1,     v1.x * invh);
                atomicAdd(d1 + 1, v1.y * invh);
            }
        }
        if (MODE == 1) {
            sl += __shfl_xor_sync(0xFFFFFFFF, sl, 1);
            sl += __shfl_xor_sync(0xFFFFFFFF, sl, 2);
            sh += __shfl_xor_sync(0xFFFFFFFF, sh, 1);
            sh += __shfl_xor_sync(0xFFFFFFFF, sh, 2);
            if ((l & 3) == 0) {
                atomicAdd(&rsp[rA], sl);
                atomicAdd(&rsp[rA + 8], sh);
            }
        }
    }
}

// ---------------- fused gemv: g1, bias2, zero wpf ----------------
__global__ __launch_bounds__(128) void gemv2_k(
    const float* __restrict__ Wk, const float* __restrict__ bq,
    const float* __restrict__ Wo, const float* __restrict__ bv,
    const float* __restrict__ bo,
    float* __restrict__ g1, float* __restrict__ bias2,
    float* __restrict__ wpf)
{
    __shared__ float red[4];
    const int o = blockIdx.x;
    const int t = threadIdx.x;

    // zero the f32 W-product accumulator: 1024 blocks x 512 floats
    {
        const size_t zi = ((size_t)(blockIdx.y * 512 + blockIdx.x) * 128 + t) * 4;
        *(float4*)(wpf + zi) = make_float4(0.f, 0.f, 0.f, 0.f);
    }

    float s = 0.f;
    if (blockIdx.y == 0) {
#pragma unroll
        for (int i = 0; i < 4; i++) {
            int h = t + i * 128;
            s += Wk[o * Hq + h] * bq[h];
        }
    } else {
#pragma unroll
        for (int i = 0; i < 4; i++) {
            int h = t + i * 128;
            s += bv[h] * Wo[h * Dq + o];
        }
    }
#pragma unroll
    for (int off = 16; off > 0; off >>= 1) s += __shfl_xor_sync(0xFFFFFFFF, s, off);
    if ((t & 31) == 0) red[t >> 5] = s;
    __syncthreads();
    if (t == 0) {
        float tot = red[0] + red[1] + red[2] + red[3];
        if (blockIdx.y == 0) g1[o] = tot;
        else bias2[o] = bo[o] + tot;
    }
}

// ---------------- fused: X->fp8, c2s, rs=0, tmp = X + bias2 (2 rows/block) -------
__global__ __launch_bounds__(256) void cvt_x8_c2_k(
    const float* __restrict__ X, const float* __restrict__ g1,
    const float* __restrict__ bias2,
    uint8_t* __restrict__ X8, float* __restrict__ c2s, float* __restrict__ rs,
    float* __restrict__ tmp)
{
    __shared__ float red[2][4];
    const int t = threadIdx.x;
    const int rloc = t >> 7;
    const int ti = t & 127;
    const long long row = (long long)blockIdx.x * 2 + rloc;
    const float* p = X + row * Dq + ti * 4;
    float4 v = *(const float4*)p;
    float4 g = *(const float4*)(g1 + ti * 4);
    uint16_t w0 = f2_to_fp8x2(v.x, v.y);
    uint16_t w1 = f2_to_fp8x2(v.z, v.w);
    *(uint32_t*)(X8 + row * Dq + ti * 4) = (uint32_t)w0 | ((uint32_t)w1 << 16);
    // tmp init: residual + bias2 (split-K final accumulates on top)
    float4 b2v = *(const float4*)(bias2 + ti * 4);
    float4 tv;
    tv.x = v.x + b2v.x; tv.y = v.y + b2v.y;
    tv.z = v.z + b2v.z; tv.w = v.w + b2v.w;
    *(float4*)(tmp + row * Dq + ti * 4) = tv;
    float s = v.x * g.x + v.y * g.y + v.z * g.z + v.w * g.w;
#pragma unroll
    for (int off = 16; off > 0; off >>= 1) s += __shfl_xor_sync(0xFFFFFFFF, s, off);
    if ((ti & 31) == 0) red[rloc][ti >> 5] = s;
    __syncthreads();
    if (ti == 0) {
        float tot = red[rloc][0] + red[rloc][1] + red[rloc][2] + red[rloc][3];
        c2s[row] = tot * 0.04419417382415922f;
        rs[row] = 0.f;
    }
}

// ---------------- fused weight prep ----------------
__global__ __launch_bounds__(256) void wprep_k(
    const float* __restrict__ wq, const float* __restrict__ wk,
    const float* __restrict__ wv, const float* __restrict__ wo,
    __nv_bfloat16* __restrict__ out)
{
    const int z = blockIdx.z;
    if (z < 3) {
        const float* W = (z == 0) ? wq : (z == 1) ? wk : wv;
        __nv_bfloat16* O = out + (size_t)z * Dq * Hq;
        const size_t i = (((size_t)blockIdx.y * 16 + blockIdx.x) * 256 + threadIdx.x) * 4;
        float4 v = *(const float4*)(W + i);
        *(__nv_bfloat162*)(O + i)     = __float22bfloat162_rn(make_float2(v.x, v.y));
        *(__nv_bfloat162*)(O + i + 2) = __float22bfloat162_rn(make_float2(v.z, v.w));
    } else {
        __shared__ float t[32][33];
        __nv_bfloat16* O = out + (size_t)3 * Dq * Hq;
        const int tx = threadIdx.x & 31;
        const int ty = threadIdx.x >> 5;
        const int x = blockIdx.x * 32 + tx;
        const int y0 = blockIdx.y * 32;
#pragma unroll
        for (int i = ty; i < 32; i += 8) t[i][tx] = wo[(y0 + i) * Dq + x];
        __syncthreads();
        const int ox = blockIdx.y * 32 + tx;
#pragma unroll
        for (int i = ty; i < 32; i += 8)
            O[(blockIdx.x * 32 + i) * Hq + ox] = __float2bfloat16_rn(t[tx][i]);
    }
}

// ---------------- one-pass LayerNorm ----------------
__global__ __launch_bounds__(128) void ln_k(
    const float* __restrict__ in, const float* __restrict__ gamma,
    const float* __restrict__ beta, float* __restrict__ out)
{
    __shared__ float s1[4], s2[4];
    const long long row = blockIdx.x;
    const int t = threadIdx.x;
    const float* p = in + row * Dq + t * 4;
    float4 v = *(const float4*)p;
    float s = v.x + v.y + v.z + v.w;
    float q = v.x * v.x + v.y * v.y + v.z * v.z + v.w * v.w;
#pragma unroll
    for (int off = 16; off > 0; off >>= 1) {
        s += __shfl_xor_sync(0xFFFFFFFF, s, off);
        q += __shfl_xor_sync(0xFFFFFFFF, q, off);
    }
    if ((t & 31) == 0) { s1[t >> 5] = s; s2[t >> 5] = q; }
    __syncthreads();
    const float sum = s1[0] + s1[1] + s1[2] + s1[3];
    const float sq  = s2[0] + s2[1] + s2[2] + s2[3];
    const float mu  = sum * (1.f / Dq);
    const float var = sq * (1.f / Dq) - mu * mu;
    const float inv = rsqrtf(var + 1e-5f);
    float4 g = *(const float4*)(gamma + t * 4);
    float4 b = *(const float4*)(beta + t * 4);
    float4 o;
    o.x = (v.x - mu) * inv * g.x + b.x;
    o.y = (v.y - mu) * inv * g.y + b.y;
    o.z = (v.z - mu) * inv * g.z + b.z;
    o.w = (v.w - mu) * inv * g.w + b.w;
    *(float4*)(out + row * Dq + t * 4) = o;
}

// ---------------- launch ----------------
extern "C" void kernel_launch(void* const* d_in, const int* in_sizes, int n_in,
                              void* d_out, int out_size)
{
    const float* X   = (const float*)d_in[0];
    const float* Wq  = (const float*)d_in[1];
    const float* bqp = (const float*)d_in[2];
    const float* Wk  = (const float*)d_in[3];
    const float* Wv  = (const float*)d_in[5];
    const float* bvp = (const float*)d_in[6];
    const float* Wo  = (const float*)d_in[7];
    const float* bop = (const float*)d_in[8];
    const float* ga  = (const float*)d_in[9];
    const float* be  = (const float*)d_in[10];
    float* out = (float*)d_out;

    void *px8, *py8, *pu8T, *pe8, *prs, *pwb, *pwpf, *pwpp8, *pwp8, *pg1, *pc2s, *pb2, *ptmp;
    cudaGetSymbolAddress(&px8, g_x8);
    cudaGetSymbolAddress(&py8, g_y8);
    cudaGetSymbolAddress(&pu8T, g_u8T);
    cudaGetSymbolAddress(&pe8, g_e8);
    cudaGetSymbolAddress(&prs, g_rs);
    cudaGetSymbolAddress(&pwb, g_wb);
    cudaGetSymbolAddress(&pwpf, g_wpf);
    cudaGetSymbolAddress(&pwpp8, g_wpp8);
    cudaGetSymbolAddress(&pwp8, g_wp8);
    cudaGetSymbolAddress(&pg1, g_g1);
    cudaGetSymbolAddress(&pc2s, g_c2s);
    cudaGetSymbolAddress(&pb2, g_bias2);
    cudaGetSymbolAddress(&ptmp, g_tmp);
    uint8_t* x8   = (uint8_t*)px8;
    uint8_t* y8   = (uint8_t*)py8;
    uint8_t* u8T  = (uint8_t*)pu8T;
    uint8_t* e8   = (uint8_t*)pe8;
    float*   rs   = (float*)prs;
    __nv_bfloat16* wb = (__nv_bfloat16*)pwb;
    float*   wpf  = (float*)pwpf;
    uint8_t* wpp8 = (uint8_t*)pwpp8;
    uint8_t* wp8  = (uint8_t*)pwp8;
    float*   g1   = (float*)pg1;
    float*   c2s  = (float*)pc2s;
    float*   b2   = (float*)pb2;
    float*   tmp  = (float*)ptmp;
    __nv_bfloat16* Wq_b  = wb;
    __nv_bfloat16* Wk_b  = wb + (size_t)Dq * Hq;
    __nv_bfloat16* Wv_b  = wb + (size_t)2 * Dq * Hq;
    __nv_bfloat16* WoT_b = wb + (size_t)3 * Dq * Hq;

    cudaFuncSetAttribute(mma_gemm_w2s,   cudaFuncAttributeMaxDynamicSharedMemorySize, SMEM_TOTAL);
    cudaFuncSetAttribute(mma_gemm_f8_yu, cudaFuncAttributeMaxDynamicSharedMemorySize, SMEM_TOTAL);
    cudaFuncSetAttribute(mma_gemm_f8<1>, cudaFuncAttributeMaxDynamicSharedMemorySize, SMEM_TOTAL);
    cudaFuncSetAttribute(mma_gemm_f8<2>, cudaFuncAttributeMaxDynamicSharedMemorySize, SMEM_TOTAL);

    const float inv_sqrt_h = 0.04419417382415922f;  // 1/sqrt(512)
    dim3 blk(256);

    // 0. prep (3 launches); cvt_x8_c2 also initializes tmp = X + bias2
    gemv2_k<<<dim3(512, 2), 128>>>(Wk, bqp, Wo, bvp, bop, g1, b2, wpf);
    cvt_x8_c2_k<<<ROWS / 2, blk>>>(X, g1, b2, x8, c2s, rs, tmp);
    wprep_k<<<dim3(16, 16, 4), blk>>>(Wq, Wk, Wv, Wo, wb);

    // 1. split-K weight products (f32 atomic accumulate), then convert x16 -> fp8
    mma_gemm_w2s<<<dim3(4, 4, 8), blk, SMEM_TOTAL>>>(Wk_b, Wq_b, WoT_b, Wv_b, wpf);
    cvt_wp_k<<<dim3(256, 2), blk>>>(wpf, wpp8, wp8);

    // 2. batched y + u
    mma_gemm_f8_yu<<<dim3(4, 128, 2), blk, SMEM_TOTAL>>>(x8, wpp8, wp8, y8, u8T);

    // 3. e8 = fp8(8*exp(y8 @ x8^T / sqrt(H) + c2s[col])); rs += row sums
    mma_gemm_f8<1><<<dim3(Nq / 128, Nq / 128, Bq), blk, SMEM_TOTAL>>>(
        y8, x8, e8, rs, c2s,
        Dq, Dq, Dq, Nq,
        (long long)Nq * Dq, (long long)Nq * Dq, (long long)Nq * Nq, inv_sqrt_h);

    // 4. split-K final: tmp += (e8 @ u8T)_ks / rs[row]   (z = bz*4 + ks)
    mma_gemm_f8<2><<<dim3(Dq / 128, Nq / 128, Bq * 4), blk, SMEM_TOTAL>>>(
        e8, u8T, tmp, rs, nullptr,
        512, Nq, ROWS, Dq,
        (long long)Nq * Nq, (long long)Nq, (long long)Nq * Dq, 1.f);

    // 5. LayerNorm
    ln_k<<<ROWS, 128>>>(tmp, ga, be, out);
}

// round 16
// speedup vs baseline: 1.0353x; 1.0353x over previous
#include <cuda_runtime.h>
#include <cuda_bf16.h>
#include <cuda_fp8.h>
#include <cstdint>
#include <math_constants.h>

// ---------------- problem constants ----------------
#define Bq 8
#define Nq 2048
#define Dq 512
#define Hq 512
#define ROWS (Bq * Nq)          // 16384

// ---------------- scratch (device globals) ----------------
__device__ uint8_t g_x8[(size_t)ROWS * Dq];              // X in fp8
__device__ uint8_t g_y8[(size_t)ROWS * Dq];              // y = X@W'' fp8
__device__ uint8_t g_u8T[(size_t)Dq * ROWS];             // u^T = (X@W')^T fp8
__device__ uint8_t g_e8[(size_t)Bq * Nq * Nq];           // exp(scores)*8 fp8
__device__ float g_rs[(size_t)ROWS];                     // row sums of 8*exp
__device__ __nv_bfloat16 g_wb[(size_t)4 * Dq * Hq];      // Wq_b, Wk_b, Wv_b, WoT_b
__device__ float g_wpf[(size_t)2 * Dq * Dq];             // f32 accum for W products
__device__ uint8_t g_wpp8[(size_t)Dq * Dq];              // (W''^T)*16 fp8
__device__ uint8_t g_wp8[(size_t)Dq * Dq];               // (W'^T)*16 fp8
__device__ float g_g1[Dq];                               // Wk @ bq
__device__ float g_c2s[(size_t)ROWS];                    // (X @ g1)/sqrt(H)
__device__ float g_bias2[Dq];                            // bo + bv@Wo
__device__ float g_tmp[(size_t)ROWS * Dq];               // pre-LN fp32

// ---------------- helpers ----------------
__device__ __forceinline__ uint32_t smem_u32(const void* p) {
    uint32_t a;
    asm("{ .reg .u64 t; cvta.to.shared.u64 t, %1; cvt.u32.u64 %0, t; }" : "=r"(a) : "l"(p));
    return a;
}
#define LDSM_X4(r0, r1, r2, r3, addr) \
    asm volatile("ldmatrix.sync.aligned.m8n8.x4.shared.b16 {%0,%1,%2,%3}, [%4];" \
        : "=r"(r0), "=r"(r1), "=r"(r2), "=r"(r3) : "r"(addr))
#define CP_ASYNC16(dst, src) \
    asm volatile("cp.async.cg.shared.global [%0], [%1], 16;" :: "r"(dst), "l"(src))
#define CP_COMMIT() asm volatile("cp.async.commit_group;" ::: "memory")
#define CP_WAIT(n)  asm volatile("cp.async.wait_group %0;" :: "n"(n) : "memory")

__device__ __forceinline__ void mma_bf16(float* d, const uint32_t* a,
                                         uint32_t b0, uint32_t b1) {
    asm volatile(
        "mma.sync.aligned.m16n8k16.row.col.f32.bf16.bf16.f32 "
        "{%0,%1,%2,%3}, {%4,%5,%6,%7}, {%8,%9}, {%0,%1,%2,%3};"
        : "+f"(d[0]), "+f"(d[1]), "+f"(d[2]), "+f"(d[3])
        : "r"(a[0]), "r"(a[1]), "r"(a[2]), "r"(a[3]), "r"(b0), "r"(b1));
}
__device__ __forceinline__ void mma_fp8(float* d, const uint32_t* a,
                                        uint32_t b0, uint32_t b1) {
    asm volatile(
        "mma.sync.aligned.m16n8k32.row.col.f32.e4m3.e4m3.f32 "
        "{%0,%1,%2,%3}, {%4,%5,%6,%7}, {%8,%9}, {%0,%1,%2,%3};"
        : "+f"(d[0]), "+f"(d[1]), "+f"(d[2]), "+f"(d[3])
        : "r"(a[0]), "r"(a[1]), "r"(a[2]), "r"(a[3]), "r"(b0), "r"(b1));
}
__device__ __forceinline__ uint16_t f2_to_fp8x2(float x, float y) {
    return (uint16_t)__nv_cvt_float2_to_fp8x2(make_float2(x, y),
                                              __NV_SATFINITE, __NV_E4M3);
}

// ---------------- shared tiling constants ----------------
#define RPAD_B 80
#define HALF_B (128 * RPAD_B)                     // 10240
#define STAGE_T (2 * HALF_B)                      // 20480
#define NSTAGE 4
#define SMEM_TOTAL (NSTAGE * STAGE_T)             // 81920 (dynamic)

// ===================== split-K bf16 weight products =====================
// grid (4,4,8): z = prod*4 + kslice. outf[prod] += A @ B^T over K chunk of 128.
__global__ __launch_bounds__(256) void mma_gemm_w2s(
    const __nv_bfloat16* __restrict__ A0, const __nv_bfloat16* __restrict__ B0,
    const __nv_bfloat16* __restrict__ A1, const __nv_bfloat16* __restrict__ B1,
    float* __restrict__ outf)
{
    extern __shared__ char smem[];
    const uint32_t sb = smem_u32(smem);
    const int tid = threadIdx.x;
    const int wid = tid >> 5;
    const int l   = tid & 31;
    const int wm  = wid & 1;
    const int wn  = wid >> 1;
    const int prod = blockIdx.z >> 2;
    const int ks   = blockIdx.z & 3;
    const int row0 = blockIdx.y * 128;
    const int col0 = blockIdx.x * 128;

    const __nv_bfloat16* A = (prod == 0) ? A0 : A1;
    const __nv_bfloat16* B = (prod == 0) ? B0 : B1;
    float* C = outf + (size_t)prod * Dq * Dq;
    const int lda = Hq, ldb = Hq;
    const int k0 = ks * 128;

    A += (long long)row0 * lda;
    B += (long long)col0 * ldb;

    const int r0  = tid >> 2;
    const int c16 = tid & 3;
    const __nv_bfloat16* Ag = A + (long long)r0 * lda + c16 * 8 + k0;
    const __nv_bfloat16* Bg = B + (long long)r0 * ldb + c16 * 8 + k0;
    const uint32_t dstA = sb + (uint32_t)(r0 * RPAD_B + c16 * 16);
    const uint32_t dstB = dstA + HALF_B;

    const uint32_t a_off = sb
        + (uint32_t)((wm * 64 + (l & 15)) * RPAD_B + ((l >> 4) & 1) * 16);
    const uint32_t b_off = sb + HALF_B
        + (uint32_t)((wn * 32 + (l & 15)) * RPAD_B + ((l >> 4) & 1) * 16);

    float acc[4][4][4];
#pragma unroll
    for (int mt = 0; mt < 4; mt++)
#pragma unroll
        for (int nt = 0; nt < 4; nt++)
#pragma unroll
            for (int i = 0; i < 4; i++) acc[mt][nt][i] = 0.f;

    auto issue_stage = [&](int s) {
        const int buf = s & (NSTAGE - 1);
        const __nv_bfloat16* ap = Ag + s * 32;
        const __nv_bfloat16* bp = Bg + s * 32;
        const uint32_t da = dstA + buf * STAGE_T;
        const uint32_t db = dstB + buf * STAGE_T;
#pragma unroll
        for (int i = 0; i < 2; i++) {
            CP_ASYNC16(da + i * 64 * RPAD_B, ap + (long long)(64 * i) * lda);
            CP_ASYNC16(db + i * 64 * RPAD_B, bp + (long long)(64 * i) * ldb);
        }
    };
    auto compute_stage = [&](int buf) {
        const uint32_t ab = a_off + buf * STAGE_T;
        const uint32_t bb = b_off + buf * STAGE_T;
#pragma unroll
        for (int kb = 0; kb < 2; kb++) {
            uint32_t afr[4][4], bfr[2][4];
#pragma unroll
            for (int mt = 0; mt < 4; mt++)
                LDSM_X4(afr[mt][0], afr[mt][1], afr[mt][2], afr[mt][3],
                        ab + mt * (16 * RPAD_B) + kb * 32);
#pragma unroll
            for (int t = 0; t < 2; t++)
                LDSM_X4(bfr[t][0], bfr[t][1], bfr[t][2], bfr[t][3],
                        bb + t * (16 * RPAD_B) + kb * 32);
#pragma unroll
            for (int mt = 0; mt < 4; mt++)
#pragma unroll
                for (int nt = 0; nt < 4; nt++)
                    mma_bf16(acc[mt][nt], afr[mt],
                             bfr[nt >> 1][nt & 1], bfr[nt >> 1][2 + (nt & 1)]);
        }
    };

    const int nst = 4;                             // 128 / 32
#pragma unroll
    for (int s = 0; s < NSTAGE - 1; s++) { issue_stage(s); CP_COMMIT(); }
    for (int s = 0; s < nst; s++) {
        CP_WAIT(NSTAGE - 2);
        __syncthreads();
        if (s + NSTAGE - 1 < nst) issue_stage(s + NSTAGE - 1);
        CP_COMMIT();
        compute_stage(s & (NSTAGE - 1));
    }

    const int lr  = l >> 2;
    const int lc2 = (l & 3) * 2;
#pragma unroll
    for (int mt = 0; mt < 4; mt++) {
        const int rA = row0 + wm * 64 + mt * 16 + lr;
#pragma unroll
        for (int nt = 0; nt < 4; nt++) {
            const int cA = col0 + wn * 32 + nt * 8 + lc2;
            atomicAdd(&C[(size_t)rA * Dq + cA],       acc[mt][nt][0]);
            atomicAdd(&C[(size_t)rA * Dq + cA + 1],   acc[mt][nt][1]);
            atomicAdd(&C[(size_t)(rA + 8) * Dq + cA],     acc[mt][nt][2]);
            atomicAdd(&C[(size_t)(rA + 8) * Dq + cA + 1], acc[mt][nt][3]);
        }
    }
}

// ---------------- convert f32 W products -> fp8 x16 ----------------
__global__ __launch_bounds__(256) void cvt_wp_k(
    const float* __restrict__ wpf, uint8_t* __restrict__ wpp8,
    uint8_t* __restrict__ wp8)
{
    const int prod = blockIdx.y;
    const size_t i = ((size_t)blockIdx.x * 256 + threadIdx.x) * 4;
    float4 v = *(const float4*)(wpf + (size_t)prod * Dq * Dq + i);
    uint16_t w0 = f2_to_fp8x2(v.x * 16.f, v.y * 16.f);
    uint16_t w1 = f2_to_fp8x2(v.z * 16.f, v.w * 16.f);
    uint8_t* O = prod ? wp8 : wpp8;
    *(uint32_t*)(O + i) = (uint32_t)w0 | ((uint32_t)w1 << 16);
}

// ===================== fp8 GEMM: y and u batched (z=2) =====================
// z=0: y8[M=ROWS,N=512] = fp8((x8 @ wpp^T)/16)
// z=1: u8T[M=512,N=ROWS] = fp8((wp @ x8^T)/16)
__global__ __launch_bounds__(256) void mma_gemm_f8_yu(
    const uint8_t* __restrict__ x8, const uint8_t* __restrict__ wpp,
    const uint8_t* __restrict__ wp,
    uint8_t* __restrict__ y8, uint8_t* __restrict__ u8T)
{
    extern __shared__ char smem[];
    const uint32_t sb = smem_u32(smem);
    const int tid = threadIdx.x;
    const int wid = tid >> 5;
    const int l   = tid & 31;
    const int wm  = wid & 1;
    const int wn  = wid >> 1;

    const uint8_t* A;
    const uint8_t* B;
    uint8_t* C;
    int ldc, row0, col0;
    if (blockIdx.z == 0) {
        A = x8; B = wpp; C = y8; ldc = Dq;
        row0 = blockIdx.y * 128; col0 = blockIdx.x * 128;
    } else {
        A = wp; B = x8; C = u8T; ldc = ROWS;
        row0 = blockIdx.x * 128; col0 = blockIdx.y * 128;
    }
    const int lda = Dq, ldb = Dq, K = Dq;
    const float alpha = 1.f / 16.f;

    A += (long long)row0 * lda;
    B += (long long)col0 * ldb;
    const long long cbase = (long long)row0 * ldc + col0;

    const int r0  = tid >> 2;
    const int c16 = tid & 3;
    const uint8_t* Ag = A + (long long)r0 * lda + c16 * 16;
    const uint8_t* Bg = B + (long long)r0 * ldb + c16 * 16;
    const uint32_t dstA = sb + (uint32_t)(r0 * RPAD_B + c16 * 16);
    const uint32_t dstB = dstA + HALF_B;

    const uint32_t a_off = sb
        + (uint32_t)((wm * 64 + (l & 15)) * RPAD_B + ((l >> 4) & 1) * 16);
    const uint32_t b_off = sb + HALF_B
        + (uint32_t)((wn * 32 + (l & 15)) * RPAD_B + ((l >> 4) & 1) * 16);

    float acc[4][4][4];
#pragma unroll
    for (int mt = 0; mt < 4; mt++)
#pragma unroll
        for (int nt = 0; nt < 4; nt++)
#pragma unroll
            for (int i = 0; i < 4; i++) acc[mt][nt][i] = 0.f;

    auto issue_stage = [&](int s) {
        const int buf = s & (NSTAGE - 1);
        const uint8_t* ap = Ag + s * 64;
        const uint8_t* bp = Bg + s * 64;
        const uint32_t da = dstA + buf * STAGE_T;
        const uint32_t db = dstB + buf * STAGE_T;
#pragma unroll
        for (int i = 0; i < 2; i++) {
            CP_ASYNC16(da + i * 64 * RPAD_B, ap + (long long)(64 * i) * lda);
            CP_ASYNC16(db + i * 64 * RPAD_B, bp + (long long)(64 * i) * ldb);
        }
    };
    auto compute_stage = [&](int buf) {
        const uint32_t ab = a_off + buf * STAGE_T;
        const uint32_t bb = b_off + buf * STAGE_T;
#pragma unroll
        for (int kb = 0; kb < 2; kb++) {
            uint32_t afr[4][4], bfr[2][4];
#pragma unroll
            for (int mt = 0; mt < 4; mt++)
                LDSM_X4(afr[mt][0], afr[mt][1], afr[mt][2], afr[mt][3],
                        ab + mt * (16 * RPAD_B) + kb * 32);
#pragma unroll
            for (int t = 0; t < 2; t++)
                LDSM_X4(bfr[t][0], bfr[t][1], bfr[t][2], bfr[t][3],
                        bb + t * (16 * RPAD_B) + kb * 32);
#pragma unroll
            for (int mt = 0; mt < 4; mt++)
#pragma unroll
                for (int nt = 0; nt < 4; nt++)
                    mma_fp8(acc[mt][nt], afr[mt],
                            bfr[nt >> 1][nt & 1], bfr[nt >> 1][2 + (nt & 1)]);
        }
    };

    const int nst = K >> 6;
#pragma unroll
    for (int s = 0; s < NSTAGE - 1; s++) { issue_stage(s); CP_COMMIT(); }
    for (int s = 0; s < nst; s++) {
        CP_WAIT(NSTAGE - 2);
        __syncthreads();
        if (s + NSTAGE - 1 < nst) issue_stage(s + NSTAGE - 1);
        CP_COMMIT();
        compute_stage(s & (NSTAGE - 1));
    }

    const int lr  = l >> 2;
    const int lc2 = (l & 3) * 2;
#pragma unroll
    for (int mt = 0; mt < 4; mt++) {
        const int rA = wm * 64 + mt * 16 + lr;
#pragma unroll
        for (int nt = 0; nt < 4; nt++) {
            const int cA = wn * 32 + nt * 8 + lc2;
            *(uint16_t*)(C + cbase + (long long)rA * ldc + cA) =
                f2_to_fp8x2(acc[mt][nt][0] * alpha, acc[mt][nt][1] * alpha);
            *(uint16_t*)(C + cbase + (long long)(rA + 8) * ldc + cA) =
                f2_to_fp8x2(acc[mt][nt][2] * alpha, acc[mt][nt][3] * alpha);
        }
    }
}

// ===================== fp8 GEMM (scores / final) =====================
// MODE 1: C = fp8(8*exp(alpha*acc + c2[col])); rs += row sums   (scores)
// MODE 2: C = f32(acc/rs[row] + bias2[col] + X_resid)           (final pre-LN)
template<int MODE>
__global__ __launch_bounds__(256) void mma_gemm_f8(
    const uint8_t* __restrict__ A, const uint8_t* __restrict__ B,
    void* __restrict__ Cv, float* __restrict__ rs,
    const float* __restrict__ c2, const float* __restrict__ bias2,
    const float* __restrict__ resid,
    int K, int lda, int ldb, int ldc,
    long long sA, long long sB, long long sC, float alpha)
{
    extern __shared__ char smem[];
    const uint32_t sb = smem_u32(smem);
    const int tid = threadIdx.x;
    const int wid = tid >> 5;
    const int l   = tid & 31;
    const int wm  = wid & 1;
    const int wn  = wid >> 1;
    const int bz  = blockIdx.z;
    const int row0 = blockIdx.y * 128;
    const int col0 = blockIdx.x * 128;

    A += (long long)bz * sA + (long long)row0 * lda;
    B += (long long)bz * sB + (long long)col0 * ldb;
    const long long cbase = (long long)bz * sC + (long long)row0 * ldc + col0;
    float* rsp = rs ? (rs + (long long)bz * Nq + row0) : nullptr;
    const float* c2p = (MODE == 1) ? (c2 + (long long)bz * Nq + col0) : nullptr;
    const float* Rp = (MODE == 2) ? (resid + cbase) : nullptr;

    const int r0  = tid >> 2;
    const int c16 = tid & 3;
    const uint8_t* Ag = A + (long long)r0 * lda + c16 * 16;
    const uint8_t* Bg = B + (long long)r0 * ldb + c16 * 16;
    const uint32_t dstA = sb + (uint32_t)(r0 * RPAD_B + c16 * 16);
    const uint32_t dstB = dstA + HALF_B;

    const uint32_t a_off = sb
        + (uint32_t)((wm * 64 + (l & 15)) * RPAD_B + ((l >> 4) & 1) * 16);
    const uint32_t b_off = sb + HALF_B
        + (uint32_t)((wn * 32 + (l & 15)) * RPAD_B + ((l >> 4) & 1) * 16);

    float acc[4][4][4];
#pragma unroll
    for (int mt = 0; mt < 4; mt++)
#pragma unroll
        for (int nt = 0; nt < 4; nt++)
#pragma unroll
            for (int i = 0; i < 4; i++) acc[mt][nt][i] = 0.f;

    auto issue_stage = [&](int s) {
        const int buf = s & (NSTAGE - 1);
        const uint8_t* ap = Ag + s * 64;
        const uint8_t* bp = Bg + s * 64;
        const uint32_t da = dstA + buf * STAGE_T;
        const uint32_t db = dstB + buf * STAGE_T;
#pragma unroll
        for (int i = 0; i < 2; i++) {
            CP_ASYNC16(da + i * 64 * RPAD_B, ap + (long long)(64 * i) * lda);
            CP_ASYNC16(db + i * 64 * RPAD_B, bp + (long long)(64 * i) * ldb);
        }
    };
    auto compute_stage = [&](int buf) {
        const uint32_t ab = a_off + buf * STAGE_T;
        const uint32_t bb = b_off + buf * STAGE_T;
#pragma unroll
        for (int kb = 0; kb < 2; kb++) {
            uint32_t afr[4][4], bfr[2][4];
#pragma unroll
            for (int mt = 0; mt < 4; mt++)
                LDSM_X4(afr[mt][0], afr[mt][1], afr[mt][2], afr[mt][3],
                        ab + mt * (16 * RPAD_B) + kb * 32);
#pragma unroll
            for (int t = 0; t < 2; t++)
                LDSM_X4(bfr[t][0], bfr[t][1], bfr[t][2], bfr[t][3],
                        bb + t * (16 * RPAD_B) + kb * 32);
#pragma unroll
            for (int mt = 0; mt < 4; mt++)
#pragma unroll
                for (int nt = 0; nt < 4; nt++)
                    mma_fp8(acc[mt][nt], afr[mt],
                            bfr[nt >> 1][nt & 1], bfr[nt >> 1][2 + (nt & 1)]);
        }
    };

    const int nst = K >> 6;
#pragma unroll
    for (int s = 0; s < NSTAGE - 1; s++) { issue_stage(s); CP_COMMIT(); }
    for (int s = 0; s < nst; s++) {
        CP_WAIT(NSTAGE - 2);
        __syncthreads();
        if (s + NSTAGE - 1 < nst) issue_stage(s + NSTAGE - 1);
        CP_COMMIT();
        compute_stage(s & (NSTAGE - 1));
    }

    uint8_t* C8 = (uint8_t*)Cv;
    float* Cf = (float*)Cv;
    const int lr  = l >> 2;
    const int lc2 = (l & 3) * 2;
#pragma unroll
    for (int mt = 0; mt < 4; mt++) {
        const int rA = wm * 64 + mt * 16 + lr;
        float sl = 0.f, sh = 0.f;
        float invl = 1.f, invh = 1.f;
        if (MODE == 2) { invl = 1.f / rsp[rA]; invh = 1.f / rsp[rA + 8]; }
#pragma unroll
        for (int nt = 0; nt < 4; nt++) {
            const int cA = wn * 32 + nt * 8 + lc2;
            float2 v0, v1;
            v0.x = acc[mt][nt][0] * alpha; v0.y = acc[mt][nt][1] * alpha;
            v1.x = acc[mt][nt][2] * alpha; v1.y = acc[mt][nt][3] * alpha;
            if (MODE == 1) {
                float2 cc = *(const float2*)(c2p + cA);
                v0.x = __expf(v0.x + cc.x) * 8.f;
                v0.y = __expf(v0.y + cc.y) * 8.f;
                v1.x = __expf(v1.x + cc.x) * 8.f;
                v1.y = __expf(v1.y + cc.y) * 8.f;
                sl += v0.x + v0.y;
                sh += v1.x + v1.y;
                *(uint16_t*)(C8 + cbase + (long long)rA * ldc + cA) =
                    f2_to_fp8x2(v0.x, v0.y);
                *(uint16_t*)(C8 + cbase + (long long)(rA + 8) * ldc + cA) =
                    f2_to_fp8x2(v1.x, v1.y);
            } else {
                float2 bb2 = *(const float2*)(bias2 + col0 + cA);
                float2 q0 = *(const float2*)(Rp + (long long)rA * ldc + cA);
                float2 q1 = *(const float2*)(Rp + (long long)(rA + 8) * ldc + cA);
                v0.x = v0.x * invl + bb2.x + q0.x;
                v0.y = v0.y * invl + bb2.y + q0.y;
                v1.x = v1.x * invh + bb2.x + q1.x;
                v1.y = v1.y * invh + bb2.y + q1.y;
                *(float2*)(Cf + cbase + (long long)rA * ldc + cA) = v0;
                *(float2*)(Cf + cbase + (long long)(rA + 8) * ldc + cA) = v1;
            }
        }
        if (MODE == 1) {
            sl += __shfl_xor_sync(0xFFFFFFFF, sl, 1);
            sl += __shfl_xor_sync(0xFFFFFFFF, sl, 2);
            sh += __shfl_xor_sync(0xFFFFFFFF, sh, 1);
            sh += __shfl_xor_sync(0xFFFFFFFF, sh, 2);
            if ((l & 3) == 0) {
                atomicAdd(&rsp[rA], sl);
                atomicAdd(&rsp[rA + 8], sh);
            }
        }
    }
}

// ---------------- fused gemv: g1, bias2, zero wpf ----------------
__global__ __launch_bounds__(128) void gemv2_k(
    const float* __restrict__ Wk, const float* __restrict__ bq,
    const float* __restrict__ Wo, const float* __restrict__ bv,
    const float* __restrict__ bo,
    float* __restrict__ g1, float* __restrict__ bias2,
    float* __restrict__ wpf)
{
    __shared__ float red[4];
    const int o = blockIdx.x;
    const int t = threadIdx.x;

    // zero the f32 W-product accumulator: 1024 blocks x 512 floats
    {
        const size_t zi = ((size_t)(blockIdx.y * 512 + blockIdx.x) * 128 + t) * 4;
        *(float4*)(wpf + zi) = make_float4(0.f, 0.f, 0.f, 0.f);
    }

    float s = 0.f;
    if (blockIdx.y == 0) {
#pragma unroll
        for (int i = 0; i < 4; i++) {
            int h = t + i * 128;
            s += Wk[o * Hq + h] * bq[h];
        }
    } else {
#pragma unroll
        for (int i = 0; i < 4; i++) {
            int h = t + i * 128;
            s += bv[h] * Wo[h * Dq + o];
        }
    }
#pragma unroll
    for (int off = 16; off > 0; off >>= 1) s += __shfl_xor_sync(0xFFFFFFFF, s, off);
    if ((t & 31) == 0) red[t >> 5] = s;
    __syncthreads();
    if (t == 0) {
        float tot = red[0] + red[1] + red[2] + red[3];
        if (blockIdx.y == 0) g1[o] = tot;
        else bias2[o] = bo[o] + tot;
    }
}

// ---------------- fused: X->fp8, c2s, rs=0 (2 rows/block) ----------------
__global__ __launch_bounds__(256) void cvt_x8_c2_k(
    const float* __restrict__ X, const float* __restrict__ g1,
    uint8_t* __restrict__ X8, float* __restrict__ c2s, float* __restrict__ rs)
{
    __shared__ float red[2][4];
    const int t = threadIdx.x;
    const int rloc = t >> 7;
    const int ti = t & 127;
    const long long row = (long long)blockIdx.x * 2 + rloc;
    const float* p = X + row * Dq + ti * 4;
    float4 v = *(const float4*)p;
    float4 g = *(const float4*)(g1 + ti * 4);
    uint16_t w0 = f2_to_fp8x2(v.x, v.y);
    uint16_t w1 = f2_to_fp8x2(v.z, v.w);
    *(uint32_t*)(X8 + row * Dq + ti * 4) = (uint32_t)w0 | ((uint32_t)w1 << 16);
    float s = v.x * g.x + v.y * g.y + v.z * g.z + v.w * g.w;
#pragma unroll
    for (int off = 16; off > 0; off >>= 1) s += __shfl_xor_sync(0xFFFFFFFF, s, off);
    if ((ti & 31) == 0) red[rloc][ti >> 5] = s;
    __syncthreads();
    if (ti == 0) {
        float tot = red[rloc][0] + red[rloc][1] + red[rloc][2] + red[rloc][3];
        c2s[row] = tot * 0.04419417382415922f;
        rs[row] = 0.f;
    }
}

// ---------------- fused weight prep ----------------
__global__ __launch_bounds__(256) void wprep_k(
    const float* __restrict__ wq, const float* __restrict__ wk,
    const float* __restrict__ wv, const float* __restrict__ wo,
    __nv_bfloat16* __restrict__ out)
{
    const int z = blockIdx.z;
    if (z < 3) {
        const float* W = (z == 0) ? wq : (z == 1) ? wk : wv;
        __nv_bfloat16* O = out + (size_t)z * Dq * Hq;
        const size_t i = (((size_t)blockIdx.y * 16 + blockIdx.x) * 256 + threadIdx.x) * 4;
        float4 v = *(const float4*)(W + i);
        *(__nv_bfloat162*)(O + i)     = __float22bfloat162_rn(make_float2(v.x, v.y));
        *(__nv_bfloat162*)(O + i + 2) = __float22bfloat162_rn(make_float2(v.z, v.w));
    } else {
        __shared__ float t[32][33];
        __nv_bfloat16* O = out + (size_t)3 * Dq * Hq;
        const int tx = threadIdx.x & 31;
        const int ty = threadIdx.x >> 5;
        const int x = blockIdx.x * 32 + tx;
        const int y0 = blockIdx.y * 32;
#pragma unroll
        for (int i = ty; i < 32; i += 8) t[i][tx] = wo[(y0 + i) * Dq + x];
        __syncthreads();
        const int ox = blockIdx.y * 32 + tx;
#pragma unroll
        for (int i = ty; i < 32; i += 8)
            O[(blockIdx.x * 32 + i) * Hq + ox] = __float2bfloat16_rn(t[tx][i]);
    }
}

// ---------------- one-pass LayerNorm ----------------
__global__ __launch_bounds__(128) void ln_k(
    const float* __restrict__ in, const float* __restrict__ gamma,
    const float* __restrict__ beta, float* __restrict__ out)
{
    __shared__ float s1[4], s2[4];
    const long long row = blockIdx.x;
    const int t = threadIdx.x;
    const float* p = in + row * Dq + t * 4;
    float4 v = *(const float4*)p;
    float s = v.x + v.y + v.z + v.w;
    float q = v.x * v.x + v.y * v.y + v.z * v.z + v.w * v.w;
#pragma unroll
    for (int off = 16; off > 0; off >>= 1) {
        s += __shfl_xor_sync(0xFFFFFFFF, s, off);
        q += __shfl_xor_sync(0xFFFFFFFF, q, off);
    }
    if ((t & 31) == 0) { s1[t >> 5] = s; s2[t >> 5] = q; }
    __syncthreads();
    const float sum = s1[0] + s1[1] + s1[2] + s1[3];
    const float sq  = s2[0] + s2[1] + s2[2] + s2[3];
    const float mu  = sum * (1.f / Dq);
    const float var = sq * (1.f / Dq) - mu * mu;
    const float inv = rsqrtf(var + 1e-5f);
    float4 g = *(const float4*)(gamma + t * 4);
    float4 b = *(const float4*)(beta + t * 4);
    float4 o;
    o.x = (v.x - mu) * inv * g.x + b.x;
    o.y = (v.y - mu) * inv * g.y + b.y;
    o.z = (v.z - mu) * inv * g.z + b.z;
    o.w = (v.w - mu) * inv * g.w + b.w;
    *(float4*)(out + row * Dq + t * 4) = o;
}

// ---------------- launch ----------------
extern "C" void kernel_launch(void* const* d_in, const int* in_sizes, int n_in,
                              void* d_out, int out_size)
{
    const float* X   = (const float*)d_in[0];
    const float* Wq  = (const float*)d_in[1];
    const float* bqp = (const float*)d_in[2];
    const float* Wk  = (const float*)d_in[3];
    const float* Wv  = (const float*)d_in[5];
    const float* bvp = (const float*)d_in[6];
    const float* Wo  = (const float*)d_in[7];
    const float* bop = (const float*)d_in[8];
    const float* ga  = (const float*)d_in[9];
    const float* be  = (const float*)d_in[10];
    float* out = (float*)d_out;

    void *px8, *py8, *pu8T, *pe8, *prs, *pwb, *pwpf, *pwpp8, *pwp8, *pg1, *pc2s, *pb2, *ptmp;
    cudaGetSymbolAddress(&px8, g_x8);
    cudaGetSymbolAddress(&py8, g_y8);
    cudaGetSymbolAddress(&pu8T, g_u8T);
    cudaGetSymbolAddress(&pe8, g_e8);
    cudaGetSymbolAddress(&prs, g_rs);
    cudaGetSymbolAddress(&pwb, g_wb);
    cudaGetSymbolAddress(&pwpf, g_wpf);
    cudaGetSymbolAddress(&pwpp8, g_wpp8);
    cudaGetSymbolAddress(&pwp8, g_wp8);
    cudaGetSymbolAddress(&pg1, g_g1);
    cudaGetSymbolAddress(&pc2s, g_c2s);
    cudaGetSymbolAddress(&pb2, g_bias2);
    cudaGetSymbolAddress(&ptmp, g_tmp);
    uint8_t* x8   = (uint8_t*)px8;
    uint8_t* y8   = (uint8_t*)py8;
    uint8_t* u8T  = (uint8_t*)pu8T;
    uint8_t* e8   = (uint8_t*)pe8;
    float*   rs   = (float*)prs;
    __nv_bfloat16* wb = (__nv_bfloat16*)pwb;
    float*   wpf  = (float*)pwpf;
    uint8_t* wpp8 = (uint8_t*)pwpp8;
    uint8_t* wp8  = (uint8_t*)pwp8;
    float*   g1   = (float*)pg1;
    float*   c2s  = (float*)pc2s;
    float*   b2   = (float*)pb2;
    float*   tmp  = (float*)ptmp;
    __nv_bfloat16* Wq_b  = wb;
    __nv_bfloat16* Wk_b  = wb + (size_t)Dq * Hq;
    __nv_bfloat16* Wv_b  = wb + (size_t)2 * Dq * Hq;
    __nv_bfloat16* WoT_b = wb + (size_t)3 * Dq * Hq;

    cudaFuncSetAttribute(mma_gemm_w2s,   cudaFuncAttributeMaxDynamicSharedMemorySize, SMEM_TOTAL);
    cudaFuncSetAttribute(mma_gemm_f8_yu, cudaFuncAttributeMaxDynamicSharedMemorySize, SMEM_TOTAL);
    cudaFuncSetAttribute(mma_gemm_f8<1>, cudaFuncAttributeMaxDynamicSharedMemorySize, SMEM_TOTAL);
    cudaFuncSetAttribute(mma_gemm_f8<2>, cudaFuncAttributeMaxDynamicSharedMemorySize, SMEM_TOTAL);

    const float inv_sqrt_h = 0.04419417382415922f;  // 1/sqrt(512)
    dim3 blk(256);

    // 0. prep (3 launches)
    gemv2_k<<<dim3(512, 2), 128>>>(Wk, bqp, Wo, bvp, bop, g1, b2, wpf);
    cvt_x8_c2_k<<<ROWS / 2, blk>>>(X, g1, x8, c2s, rs);
    wprep_k<<<dim3(16, 16, 4), blk>>>(Wq, Wk, Wv, Wo, wb);

    // 1. split-K weight products (f32 atomic accumulate), then convert x16 -> fp8
    mma_gemm_w2s<<<dim3(4, 4, 8), blk, SMEM_TOTAL>>>(Wk_b, Wq_b, WoT_b, Wv_b, wpf);
    cvt_wp_k<<<dim3(256, 2), blk>>>(wpf, wpp8, wp8);

    // 2. batched y + u
    mma_gemm_f8_yu<<<dim3(4, 128, 2), blk, SMEM_TOTAL>>>(x8, wpp8, wp8, y8, u8T);

    // 3. e8 = fp8(8*exp(y8 @ x8^T / sqrt(H) + c2s[col])); rs += row sums
    mma_gemm_f8<1><<<dim3(Nq / 128, Nq / 128, Bq), blk, SMEM_TOTAL>>>(
        y8, x8, e8, rs, c2s, nullptr, nullptr,
        Dq, Dq, Dq, Nq,
        (long long)Nq * Dq, (long long)Nq * Dq, (long long)Nq * Nq, inv_sqrt_h);

    // 4. tmp = (e8 @ u8T)/rs + bias2[col] + X   [final pre-LN, fp32]
    mma_gemm_f8<2><<<dim3(Dq / 128, Nq / 128, Bq), blk, SMEM_TOTAL>>>(
        e8, u8T, tmp, rs, nullptr, b2, X,
        Nq, Nq, ROWS, Dq,
        (long long)Nq * Nq, (long long)Nq, (long long)Nq * Dq, 1.f);

    // 5. LayerNorm
    ln_k<<<ROWS, 128>>>(tmp, ga, be, out);
}

// round 17
// speedup vs baseline: 1.0394x; 1.0039x over previous
#include <cuda_runtime.h>
#include <cuda_bf16.h>
#include <cuda_fp8.h>
#include <cstdint>
#include <math_constants.h>

// ---------------- problem constants ----------------
#define Bq 8
#define Nq 2048
#define Dq 512
#define Hq 512
#define ROWS (Bq * Nq)          // 16384

// ---------------- scratch (device globals) ----------------
__device__ uint8_t g_x8[(size_t)ROWS * Dq];              // X in fp8
__device__ uint8_t g_y8[(size_t)ROWS * Dq];              // y = X@W'' fp8
__device__ uint8_t g_u8T[(size_t)Dq * ROWS];             // u^T = (X@W')^T fp8
__device__ uint8_t g_e8[(size_t)Bq * Nq * Nq];           // exp(scores)*8 fp8
__device__ float g_rs[(size_t)ROWS];                     // row sums of 8*exp
__device__ __nv_bfloat16 g_wb[(size_t)4 * Dq * Hq];      // Wq_b, Wk_b, Wv_b, WoT_b
__device__ float g_wpf[(size_t)2 * Dq * Dq];             // f32 accum for W products
__device__ uint8_t g_wpp8[(size_t)Dq * Dq];              // (W''^T)*16 fp8
__device__ uint8_t g_wp8[(size_t)Dq * Dq];               // (W'^T)*16 fp8
__device__ float g_g1[Dq];                               // Wk @ bq
__device__ float g_c2s[(size_t)ROWS];                    // (X @ g1) * log2e / sqrt(H)
__device__ float g_bias2[Dq];                            // bo + bv@Wo
__device__ float g_tmp[(size_t)ROWS * Dq];               // pre-LN fp32

// ---------------- helpers ----------------
__device__ __forceinline__ uint32_t smem_u32(const void* p) {
    uint32_t a;
    asm("{ .reg .u64 t; cvta.to.shared.u64 t, %1; cvt.u32.u64 %0, t; }" : "=r"(a) : "l"(p));
    return a;
}
#define LDSM_X4(r0, r1, r2, r3, addr) \
    asm volatile("ldmatrix.sync.aligned.m8n8.x4.shared.b16 {%0,%1,%2,%3}, [%4];" \
        : "=r"(r0), "=r"(r1), "=r"(r2), "=r"(r3) : "r"(addr))
#define CP_ASYNC16(dst, src) \
    asm volatile("cp.async.cg.shared.global [%0], [%1], 16;" :: "r"(dst), "l"(src))
#define CP_COMMIT() asm volatile("cp.async.commit_group;" ::: "memory")
#define CP_WAIT(n)  asm volatile("cp.async.wait_group %0;" :: "n"(n) : "memory")

__device__ __forceinline__ void mma_bf16(float* d, const uint32_t* a,
                                         uint32_t b0, uint32_t b1) {
    asm volatile(
        "mma.sync.aligned.m16n8k16.row.col.f32.bf16.bf16.f32 "
        "{%0,%1,%2,%3}, {%4,%5,%6,%7}, {%8,%9}, {%0,%1,%2,%3};"
        : "+f"(d[0]), "+f"(d[1]), "+f"(d[2]), "+f"(d[3])
        : "r"(a[0]), "r"(a[1]), "r"(a[2]), "r"(a[3]), "r"(b0), "r"(b1));
}
__device__ __forceinline__ void mma_fp8(float* d, const uint32_t* a,
                                        uint32_t b0, uint32_t b1) {
    asm volatile(
        "mma.sync.aligned.m16n8k32.row.col.f32.e4m3.e4m3.f32 "
        "{%0,%1,%2,%3}, {%4,%5,%6,%7}, {%8,%9}, {%0,%1,%2,%3};"
        : "+f"(d[0]), "+f"(d[1]), "+f"(d[2]), "+f"(d[3])
        : "r"(a[0]), "r"(a[1]), "r"(a[2]), "r"(a[3]), "r"(b0), "r"(b1));
}
__device__ __forceinline__ uint16_t f2_to_fp8x2(float x, float y) {
    return (uint16_t)__nv_cvt_float2_to_fp8x2(make_float2(x, y),
                                              __NV_SATFINITE, __NV_E4M3);
}
__device__ __forceinline__ float ex2f(float x) {
    float r;
    asm("ex2.approx.f32 %0, %1;" : "=f"(r) : "f"(x));
    return r;
}

// ---------------- shared tiling constants ----------------
#define RPAD_B 80
#define HALF_B (128 * RPAD_B)                     // 10240
#define STAGE_T (2 * HALF_B)                      // 20480
#define NSTAGE 4
#define SMEM_TOTAL (NSTAGE * STAGE_T)             // 81920 (dynamic)

// ===================== split-K bf16 weight products =====================
// grid (4,4,8): z = prod*4 + kslice. outf[prod] += A @ B^T over K chunk of 128.
__global__ __launch_bounds__(256) void mma_gemm_w2s(
    const __nv_bfloat16* __restrict__ A0, const __nv_bfloat16* __restrict__ B0,
    const __nv_bfloat16* __restrict__ A1, const __nv_bfloat16* __restrict__ B1,
    float* __restrict__ outf)
{
    extern __shared__ char smem[];
    const uint32_t sb = smem_u32(smem);
    const int tid = threadIdx.x;
    const int wid = tid >> 5;
    const int l   = tid & 31;
    const int wm  = wid & 1;
    const int wn  = wid >> 1;
    const int prod = blockIdx.z >> 2;
    const int ks   = blockIdx.z & 3;
    const int row0 = blockIdx.y * 128;
    const int col0 = blockIdx.x * 128;

    const __nv_bfloat16* A = (prod == 0) ? A0 : A1;
    const __nv_bfloat16* B = (prod == 0) ? B0 : B1;
    float* C = outf + (size_t)prod * Dq * Dq;
    const int lda = Hq, ldb = Hq;
    const int k0 = ks * 128;

    A += (long long)row0 * lda;
    B += (long long)col0 * ldb;

    const int r0  = tid >> 2;
    const int c16 = tid & 3;
    const __nv_bfloat16* Ag = A + (long long)r0 * lda + c16 * 8 + k0;
    const __nv_bfloat16* Bg = B + (long long)r0 * ldb + c16 * 8 + k0;
    const uint32_t dstA = sb + (uint32_t)(r0 * RPAD_B + c16 * 16);
    const uint32_t dstB = dstA + HALF_B;

    const uint32_t a_off = sb
        + (uint32_t)((wm * 64 + (l & 15)) * RPAD_B + ((l >> 4) & 1) * 16);
    const uint32_t b_off = sb + HALF_B
        + (uint32_t)((wn * 32 + (l & 15)) * RPAD_B + ((l >> 4) & 1) * 16);

    float acc[4][4][4];
#pragma unroll
    for (int mt = 0; mt < 4; mt++)
#pragma unroll
        for (int nt = 0; nt < 4; nt++)
#pragma unroll
            for (int i = 0; i < 4; i++) acc[mt][nt][i] = 0.f;

    auto issue_stage = [&](int s) {
        const int buf = s & (NSTAGE - 1);
        const __nv_bfloat16* ap = Ag + s * 32;
        const __nv_bfloat16* bp = Bg + s * 32;
        const uint32_t da = dstA + buf * STAGE_T;
        const uint32_t db = dstB + buf * STAGE_T;
#pragma unroll
        for (int i = 0; i < 2; i++) {
            CP_ASYNC16(da + i * 64 * RPAD_B, ap + (long long)(64 * i) * lda);
            CP_ASYNC16(db + i * 64 * RPAD_B, bp + (long long)(64 * i) * ldb);
        }
    };
    auto compute_stage = [&](int buf) {
        const uint32_t ab = a_off + buf * STAGE_T;
        const uint32_t bb = b_off + buf * STAGE_T;
#pragma unroll
        for (int kb = 0; kb < 2; kb++) {
            uint32_t afr[4][4], bfr[2][4];
#pragma unroll
            for (int mt = 0; mt < 4; mt++)
                LDSM_X4(afr[mt][0], afr[mt][1], afr[mt][2], afr[mt][3],
                        ab + mt * (16 * RPAD_B) + kb * 32);
#pragma unroll
            for (int t = 0; t < 2; t++)
                LDSM_X4(bfr[t][0], bfr[t][1], bfr[t][2], bfr[t][3],
                        bb + t * (16 * RPAD_B) + kb * 32);
#pragma unroll
            for (int mt = 0; mt < 4; mt++)
#pragma unroll
                for (int nt = 0; nt < 4; nt++)
                    mma_bf16(acc[mt][nt], afr[mt],
                             bfr[nt >> 1][nt & 1], bfr[nt >> 1][2 + (nt & 1)]);
        }
    };

    const int nst = 4;                             // 128 / 32
#pragma unroll
    for (int s = 0; s < NSTAGE - 1; s++) { issue_stage(s); CP_COMMIT(); }
    for (int s = 0; s < nst; s++) {
        CP_WAIT(NSTAGE - 2);
        __syncthreads();
        if (s + NSTAGE - 1 < nst) issue_stage(s + NSTAGE - 1);
        CP_COMMIT();
        compute_stage(s & (NSTAGE - 1));
    }

    const int lr  = l >> 2;
    const int lc2 = (l & 3) * 2;
#pragma unroll
    for (int mt = 0; mt < 4; mt++) {
        const int rA = row0 + wm * 64 + mt * 16 + lr;
#pragma unroll
        for (int nt = 0; nt < 4; nt++) {
            const int cA = col0 + wn * 32 + nt * 8 + lc2;
            atomicAdd(&C[(size_t)rA * Dq + cA],       acc[mt][nt][0]);
            atomicAdd(&C[(size_t)rA * Dq + cA + 1],   acc[mt][nt][1]);
            atomicAdd(&C[(size_t)(rA + 8) * Dq + cA],     acc[mt][nt][2]);
            atomicAdd(&C[(size_t)(rA + 8) * Dq + cA + 1], acc[mt][nt][3]);
        }
    }
}

// ---------------- convert f32 W products -> fp8 x16 ----------------
__global__ __launch_bounds__(256) void cvt_wp_k(
    const float* __restrict__ wpf, uint8_t* __restrict__ wpp8,
    uint8_t* __restrict__ wp8)
{
    const int prod = blockIdx.y;
    const size_t i = ((size_t)blockIdx.x * 256 + threadIdx.x) * 4;
    float4 v = *(const float4*)(wpf + (size_t)prod * Dq * Dq + i);
    uint16_t w0 = f2_to_fp8x2(v.x * 16.f, v.y * 16.f);
    uint16_t w1 = f2_to_fp8x2(v.z * 16.f, v.w * 16.f);
    uint8_t* O = prod ? wp8 : wpp8;
    *(uint32_t*)(O + i) = (uint32_t)w0 | ((uint32_t)w1 << 16);
}

// ===================== fp8 GEMM: y and u batched (z=2) =====================
// z=0: y8[M=ROWS,N=512] = fp8((x8 @ wpp^T)/16)
// z=1: u8T[M=512,N=ROWS] = fp8((wp @ x8^T)/16)
__global__ __launch_bounds__(256) void mma_gemm_f8_yu(
    const uint8_t* __restrict__ x8, const uint8_t* __restrict__ wpp,
    const uint8_t* __restrict__ wp,
    uint8_t* __restrict__ y8, uint8_t* __restrict__ u8T)
{
    extern __shared__ char smem[];
    const uint32_t sb = smem_u32(smem);
    const int tid = threadIdx.x;
    const int wid = tid >> 5;
    const int l   = tid & 31;
    const int wm  = wid & 1;
    const int wn  = wid >> 1;

    const uint8_t* A;
    const uint8_t* B;
    uint8_t* C;
    int ldc, row0, col0;
    if (blockIdx.z == 0) {
        A = x8; B = wpp; C = y8; ldc = Dq;
        row0 = blockIdx.y * 128; col0 = blockIdx.x * 128;
    } else {
        A = wp; B = x8; C = u8T; ldc = ROWS;
        row0 = blockIdx.x * 128; col0 = blockIdx.y * 128;
    }
    const int lda = Dq, ldb = Dq, K = Dq;
    const float alpha = 1.f / 16.f;

    A += (long long)row0 * lda;
    B += (long long)col0 * ldb;
    const long long cbase = (long long)row0 * ldc + col0;

    const int r0  = tid >> 2;
    const int c16 = tid & 3;
    const uint8_t* Ag = A + (long long)r0 * lda + c16 * 16;
    const uint8_t* Bg = B + (long long)r0 * ldb + c16 * 16;
    const uint32_t dstA = sb + (uint32_t)(r0 * RPAD_B + c16 * 16);
    const uint32_t dstB = dstA + HALF_B;

    const uint32_t a_off = sb
        + (uint32_t)((wm * 64 + (l & 15)) * RPAD_B + ((l >> 4) & 1) * 16);
    const uint32_t b_off = sb + HALF_B
        + (uint32_t)((wn * 32 + (l & 15)) * RPAD_B + ((l >> 4) & 1) * 16);

    float acc[4][4][4];
#pragma unroll
    for (int mt = 0; mt < 4; mt++)
#pragma unroll
        for (int nt = 0; nt < 4; nt++)
#pragma unroll
            for (int i = 0; i < 4; i++) acc[mt][nt][i] = 0.f;

    auto issue_stage = [&](int s) {
        const int buf = s & (NSTAGE - 1);
        const uint8_t* ap = Ag + s * 64;
        const uint8_t* bp = Bg + s * 64;
        const uint32_t da = dstA + buf * STAGE_T;
        const uint32_t db = dstB + buf * STAGE_T;
#pragma unroll
        for (int i = 0; i < 2; i++) {
            CP_ASYNC16(da + i * 64 * RPAD_B, ap + (long long)(64 * i) * lda);
            CP_ASYNC16(db + i * 64 * RPAD_B, bp + (long long)(64 * i) * ldb);
        }
    };
    auto compute_stage = [&](int buf) {
        const uint32_t ab = a_off + buf * STAGE_T;
        const uint32_t bb = b_off + buf * STAGE_T;
#pragma unroll
        for (int kb = 0; kb < 2; kb++) {
            uint32_t afr[4][4], bfr[2][4];
#pragma unroll
            for (int mt = 0; mt < 4; mt++)
                LDSM_X4(afr[mt][0], afr[mt][1], afr[mt][2], afr[mt][3],
                        ab + mt * (16 * RPAD_B) + kb * 32);
#pragma unroll
            for (int t = 0; t < 2; t++)
                LDSM_X4(bfr[t][0], bfr[t][1], bfr[t][2], bfr[t][3],
                        bb + t * (16 * RPAD_B) + kb * 32);
#pragma unroll
            for (int mt = 0; mt < 4; mt++)
#pragma unroll
                for (int nt = 0; nt < 4; nt++)
                    mma_fp8(acc[mt][nt], afr[mt],
                            bfr[nt >> 1][nt & 1], bfr[nt >> 1][2 + (nt & 1)]);
        }
    };

    const int nst = K >> 6;
#pragma unroll
    for (int s = 0; s < NSTAGE - 1; s++) { issue_stage(s); CP_COMMIT(); }
    for (int s = 0; s < nst; s++) {
        CP_WAIT(NSTAGE - 2);
        __syncthreads();
        if (s + NSTAGE - 1 < nst) issue_stage(s + NSTAGE - 1);
        CP_COMMIT();
        compute_stage(s & (NSTAGE - 1));
    }

    const int lr  = l >> 2;
    const int lc2 = (l & 3) * 2;
#pragma unroll
    for (int mt = 0; mt < 4; mt++) {
        const int rA = wm * 64 + mt * 16 + lr;
#pragma unroll
        for (int nt = 0; nt < 4; nt++) {
            const int cA = wn * 32 + nt * 8 + lc2;
            *(uint16_t*)(C + cbase + (long long)rA * ldc + cA) =
                f2_to_fp8x2(acc[mt][nt][0] * alpha, acc[mt][nt][1] * alpha);
            *(uint16_t*)(C + cbase + (long long)(rA + 8) * ldc + cA) =
                f2_to_fp8x2(acc[mt][nt][2] * alpha, acc[mt][nt][3] * alpha);
        }
    }
}

// ===================== fp8 GEMM (scores / final) =====================
// MODE 1: C = fp8(8*exp2(alpha2*acc + c2[col])); rs += row sums  (scores)
//         (alpha2 = log2e/sqrt(H), c2 pre-scaled by log2e)
// MODE 2: C = f32(acc/rs[row] + bias2[col] + X_resid)            (final pre-LN)
template<int MODE>
__global__ __launch_bounds__(256) void mma_gemm_f8(
    const uint8_t* __restrict__ A, const uint8_t* __restrict__ B,
    void* __restrict__ Cv, float* __restrict__ rs,
    const float* __restrict__ c2, const float* __restrict__ bias2,
    const float* __restrict__ resid,
    int K, int lda, int ldb, int ldc,
    long long sA, long long sB, long long sC, float alpha)
{
    extern __shared__ char smem[];
    const uint32_t sb = smem_u32(smem);
    const int tid = threadIdx.x;
    const int wid = tid >> 5;
    const int l   = tid & 31;
    const int wm  = wid & 1;
    const int wn  = wid >> 1;
    const int bz  = blockIdx.z;
    const int row0 = blockIdx.y * 128;
    const int col0 = blockIdx.x * 128;

    A += (long long)bz * sA + (long long)row0 * lda;
    B += (long long)bz * sB + (long long)col0 * ldb;
    const long long cbase = (long long)bz * sC + (long long)row0 * ldc + col0;
    float* rsp = rs ? (rs + (long long)bz * Nq + row0) : nullptr;
    const float* c2p = (MODE == 1) ? (c2 + (long long)bz * Nq + col0) : nullptr;
    const float* Rp = (MODE == 2) ? (resid + cbase) : nullptr;

    const int r0  = tid >> 2;
    const int c16 = tid & 3;
    const uint8_t* Ag = A + (long long)r0 * lda + c16 * 16;
    const uint8_t* Bg = B + (long long)r0 * ldb + c16 * 16;
    const uint32_t dstA = sb + (uint32_t)(r0 * RPAD_B + c16 * 16);
    const uint32_t dstB = dstA + HALF_B;

    const uint32_t a_off = sb
        + (uint32_t)((wm * 64 + (l & 15)) * RPAD_B + ((l >> 4) & 1) * 16);
    const uint32_t b_off = sb + HALF_B
        + (uint32_t)((wn * 32 + (l & 15)) * RPAD_B + ((l >> 4) & 1) * 16);

    float acc[4][4][4];
#pragma unroll
    for (int mt = 0; mt < 4; mt++)
#pragma unroll
        for (int nt = 0; nt < 4; nt++)
#pragma unroll
            for (int i = 0; i < 4; i++) acc[mt][nt][i] = 0.f;

    auto issue_stage = [&](int s) {
        const int buf = s & (NSTAGE - 1);
        const uint8_t* ap = Ag + s * 64;
        const uint8_t* bp = Bg + s * 64;
        const uint32_t da = dstA + buf * STAGE_T;
        const uint32_t db = dstB + buf * STAGE_T;
#pragma unroll
        for (int i = 0; i < 2; i++) {
            CP_ASYNC16(da + i * 64 * RPAD_B, ap + (long long)(64 * i) * lda);
            CP_ASYNC16(db + i * 64 * RPAD_B, bp + (long long)(64 * i) * ldb);
        }
    };
    auto compute_stage = [&](int buf) {
        const uint32_t ab = a_off + buf * STAGE_T;
        const uint32_t bb = b_off + buf * STAGE_T;
#pragma unroll
        for (int kb = 0; kb < 2; kb++) {
            uint32_t afr[4][4], bfr[2][4];
#pragma unroll
            for (int mt = 0; mt < 4; mt++)
                LDSM_X4(afr[mt][0], afr[mt][1], afr[mt][2], afr[mt][3],
                        ab + mt * (16 * RPAD_B) + kb * 32);
#pragma unroll
            for (int t = 0; t < 2; t++)
                LDSM_X4(bfr[t][0], bfr[t][1], bfr[t][2], bfr[t][3],
                        bb + t * (16 * RPAD_B) + kb * 32);
#pragma unroll
            for (int mt = 0; mt < 4; mt++)
#pragma unroll
                for (int nt = 0; nt < 4; nt++)
                    mma_fp8(acc[mt][nt], afr[mt],
                            bfr[nt >> 1][nt & 1], bfr[nt >> 1][2 + (nt & 1)]);
        }
    };

    const int nst = K >> 6;
#pragma unroll
    for (int s = 0; s < NSTAGE - 1; s++) { issue_stage(s); CP_COMMIT(); }
    for (int s = 0; s < nst; s++) {
        CP_WAIT(NSTAGE - 2);
        __syncthreads();
        if (s + NSTAGE - 1 < nst) issue_stage(s + NSTAGE - 1);
        CP_COMMIT();
        compute_stage(s & (NSTAGE - 1));
    }

    uint8_t* C8 = (uint8_t*)Cv;
    float* Cf = (float*)Cv;
    const int lr  = l >> 2;
    const int lc2 = (l & 3) * 2;
#pragma unroll
    for (int mt = 0; mt < 4; mt++) {
        const int rA = wm * 64 + mt * 16 + lr;
        float sl = 0.f, sh = 0.f;
        float invl = 1.f, invh = 1.f;
        if (MODE == 2) { invl = 1.f / rsp[rA]; invh = 1.f / rsp[rA + 8]; }
#pragma unroll
        for (int nt = 0; nt < 4; nt++) {
            const int cA = wn * 32 + nt * 8 + lc2;
            float2 v0, v1;
            v0.x = acc[mt][nt][0] * alpha; v0.y = acc[mt][nt][1] * alpha;
            v1.x = acc[mt][nt][2] * alpha; v1.y = acc[mt][nt][3] * alpha;
            if (MODE == 1) {
                float2 cc = *(const float2*)(c2p + cA);
                v0.x = ex2f(v0.x + cc.x) * 8.f;
                v0.y = ex2f(v0.y + cc.y) * 8.f;
                v1.x = ex2f(v1.x + cc.x) * 8.f;
                v1.y = ex2f(v1.y + cc.y) * 8.f;
                sl += v0.x + v0.y;
                sh += v1.x + v1.y;
                *(uint16_t*)(C8 + cbase + (long long)rA * ldc + cA) =
                    f2_to_fp8x2(v0.x, v0.y);
                *(uint16_t*)(C8 + cbase + (long long)(rA + 8) * ldc + cA) =
                    f2_to_fp8x2(v1.x, v1.y);
            } else {
                float2 bb2 = *(const float2*)(bias2 + col0 + cA);
                float2 q0 = *(const float2*)(Rp + (long long)rA * ldc + cA);
                float2 q1 = *(const float2*)(Rp + (long long)(rA + 8) * ldc + cA);
                v0.x = v0.x * invl + bb2.x + q0.x;
                v0.y = v0.y * invl + bb2.y + q0.y;
                v1.x = v1.x * invh + bb2.x + q1.x;
                v1.y = v1.y * invh + bb2.y + q1.y;
                *(float2*)(Cf + cbase + (long long)rA * ldc + cA) = v0;
                *(float2*)(Cf + cbase + (long long)(rA + 8) * ldc + cA) = v1;
            }
        }
        if (MODE == 1) {
            sl += __shfl_xor_sync(0xFFFFFFFF, sl, 1);
            sl += __shfl_xor_sync(0xFFFFFFFF, sl, 2);
            sh += __shfl_xor_sync(0xFFFFFFFF, sh, 1);
            sh += __shfl_xor_sync(0xFFFFFFFF, sh, 2);
            if ((l & 3) == 0) {
                atomicAdd(&rsp[rA], sl);
                atomicAdd(&rsp[rA + 8], sh);
            }
        }
    }
}

// ---------------- fused gemv: g1, bias2, zero wpf ----------------
__global__ __launch_bounds__(128) void gemv2_k(
    const float* __restrict__ Wk, const float* __restrict__ bq,
    const float* __restrict__ Wo, const float* __restrict__ bv,
    const float* __restrict__ bo,
    float* __restrict__ g1, float* __restrict__ bias2,
    float* __restrict__ wpf)
{
    __shared__ float red[4];
    const int o = blockIdx.x;
    const int t = threadIdx.x;

    // zero the f32 W-product accumulator: 1024 blocks x 512 floats
    {
        const size_t zi = ((size_t)(blockIdx.y * 512 + blockIdx.x) * 128 + t) * 4;
        *(float4*)(wpf + zi) = make_float4(0.f, 0.f, 0.f, 0.f);
    }

    float s = 0.f;
    if (blockIdx.y == 0) {
#pragma unroll
        for (int i = 0; i < 4; i++) {
            int h = t + i * 128;
            s += Wk[o * Hq + h] * bq[h];
        }
    } else {
#pragma unroll
        for (int i = 0; i < 4; i++) {
            int h = t + i * 128;
            s += bv[h] * Wo[h * Dq + o];
        }
    }
#pragma unroll
    for (int off = 16; off > 0; off >>= 1) s += __shfl_xor_sync(0xFFFFFFFF, s, off);
    if ((t & 31) == 0) red[t >> 5] = s;
    __syncthreads();
    if (t == 0) {
        float tot = red[0] + red[1] + red[2] + red[3];
        if (blockIdx.y == 0) g1[o] = tot;
        else bias2[o] = bo[o] + tot;
    }
}

// ---------------- fused: X->fp8, c2s (x log2e), rs=0 (2 rows/block) ----------------
__global__ __launch_bounds__(256) void cvt_x8_c2_k(
    const float* __restrict__ X, const float* __restrict__ g1,
    uint8_t* __restrict__ X8, float* __restrict__ c2s, float* __restrict__ rs)
{
    __shared__ float red[2][4];
    const int t = threadIdx.x;
    const int rloc = t >> 7;
    const int ti = t & 127;
    const long long row = (long long)blockIdx.x * 2 + rloc;
    const float* p = X + row * Dq + ti * 4;
    float4 v = *(const float4*)p;
    float4 g = *(const float4*)(g1 + ti * 4);
    uint16_t w0 = f2_to_fp8x2(v.x, v.y);
    uint16_t w1 = f2_to_fp8x2(v.z, v.w);
    *(uint32_t*)(X8 + row * Dq + ti * 4) = (uint32_t)w0 | ((uint32_t)w1 << 16);
    float s = v.x * g.x + v.y * g.y + v.z * g.z + v.w * g.w;
#pragma unroll
    for (int off = 16; off > 0; off >>= 1) s += __shfl_xor_sync(0xFFFFFFFF, s, off);
    if ((ti & 31) == 0) red[rloc][ti >> 5] = s;
    __syncthreads();
    if (ti == 0) {
        float tot = red[rloc][0] + red[rloc][1] + red[rloc][2] + red[rloc][3];
        // (1/sqrt(512)) * log2(e)  — exp folded into exp2 in the scores epilogue
        c2s[row] = tot * 0.06376237712562488f;
        rs[row] = 0.f;
    }
}

// ---------------- fused weight prep ----------------
__global__ __launch_bounds__(256) void wprep_k(
    const float* __restrict__ wq, const float* __restrict__ wk,
    const float* __restrict__ wv, const float* __restrict__ wo,
    __nv_bfloat16* __restrict__ out)
{
    const int z = blockIdx.z;
    if (z < 3) {
        const float* W = (z == 0) ? wq : (z == 1) ? wk : wv;
        __nv_bfloat16* O = out + (size_t)z * Dq * Hq;
        const size_t i = (((size_t)blockIdx.y * 16 + blockIdx.x) * 256 + threadIdx.x) * 4;
        float4 v = *(const float4*)(W + i);
        *(__nv_bfloat162*)(O + i)     = __float22bfloat162_rn(make_float2(v.x, v.y));
        *(__nv_bfloat162*)(O + i + 2) = __float22bfloat162_rn(make_float2(v.z, v.w));
    } else {
        __shared__ float t[32][33];
        __nv_bfloat16* O = out + (size_t)3 * Dq * Hq;
        const int tx = threadIdx.x & 31;
        const int ty = threadIdx.x >> 5;
        const int x = blockIdx.x * 32 + tx;
        const int y0 = blockIdx.y * 32;
#pragma unroll
        for (int i = ty; i < 32; i += 8) t[i][tx] = wo[(y0 + i) * Dq + x];
        __syncthreads();
        const int ox = blockIdx.y * 32 + tx;
#pragma unroll
        for (int i = ty; i < 32; i += 8)
            O[(blockIdx.x * 32 + i) * Hq + ox] = __float2bfloat16_rn(t[tx][i]);
    }
}

// ---------------- one-pass LayerNorm ----------------
__global__ __launch_bounds__(128) void ln_k(
    const float* __restrict__ in, const float* __restrict__ gamma,
    const float* __restrict__ beta, float* __restrict__ out)
{
    __shared__ float s1[4], s2[4];
    const long long row = blockIdx.x;
    const int t = threadIdx.x;
    const float* p = in + row * Dq + t * 4;
    float4 v = *(const float4*)p;
    float s = v.x + v.y + v.z + v.w;
    float q = v.x * v.x + v.y * v.y + v.z * v.z + v.w * v.w;
#pragma unroll
    for (int off = 16; off > 0; off >>= 1) {
        s += __shfl_xor_sync(0xFFFFFFFF, s, off);
        q += __shfl_xor_sync(0xFFFFFFFF, q, off);
    }
    if ((t & 31) == 0) { s1[t >> 5] = s; s2[t >> 5] = q; }
    __syncthreads();
    const float sum = s1[0] + s1[1] + s1[2] + s1[3];
    const float sq  = s2[0] + s2[1] + s2[2] + s2[3];
    const float mu  = sum * (1.f / Dq);
    const float var = sq * (1.f / Dq) - mu * mu;
    const float inv = rsqrtf(var + 1e-5f);
    float4 g = *(const float4*)(gamma + t * 4);
    float4 b = *(const float4*)(beta + t * 4);
    float4 o;
    o.x = (v.x - mu) * inv * g.x + b.x;
    o.y = (v.y - mu) * inv * g.y + b.y;
    o.z = (v.z - mu) * inv * g.z + b.z;
    o.w = (v.w - mu) * inv * g.w + b.w;
    *(float4*)(out + row * Dq + t * 4) = o;
}

// ---------------- launch ----------------
extern "C" void kernel_launch(void* const* d_in, const int* in_sizes, int n_in,
                              void* d_out, int out_size)
{
    const float* X   = (const float*)d_in[0];
    const float* Wq  = (const float*)d_in[1];
    const float* bqp = (const float*)d_in[2];
    const float* Wk  = (const float*)d_in[3];
    const float* Wv  = (const float*)d_in[5];
    const float* bvp = (const float*)d_in[6];
    const float* Wo  = (const float*)d_in[7];
    const float* bop = (const float*)d_in[8];
    const float* ga  = (const float*)d_in[9];
    const float* be  = (const float*)d_in[10];
    float* out = (float*)d_out;

    void *px8, *py8, *pu8T, *pe8, *prs, *pwb, *pwpf, *pwpp8, *pwp8, *pg1, *pc2s, *pb2, *ptmp;
    cudaGetSymbolAddress(&px8, g_x8);
    cudaGetSymbolAddress(&py8, g_y8);
    cudaGetSymbolAddress(&pu8T, g_u8T);
    cudaGetSymbolAddress(&pe8, g_e8);
    cudaGetSymbolAddress(&prs, g_rs);
    cudaGetSymbolAddress(&pwb, g_wb);
    cudaGetSymbolAddress(&pwpf, g_wpf);
    cudaGetSymbolAddress(&pwpp8, g_wpp8);
    cudaGetSymbolAddress(&pwp8, g_wp8);
    cudaGetSymbolAddress(&pg1, g_g1);
    cudaGetSymbolAddress(&pc2s, g_c2s);
    cudaGetSymbolAddress(&pb2, g_bias2);
    cudaGetSymbolAddress(&ptmp, g_tmp);
    uint8_t* x8   = (uint8_t*)px8;
    uint8_t* y8   = (uint8_t*)py8;
    uint8_t* u8T  = (uint8_t*)pu8T;
    uint8_t* e8   = (uint8_t*)pe8;
    float*   rs   = (float*)prs;
    __nv_bfloat16* wb = (__nv_bfloat16*)pwb;
    float*   wpf  = (float*)pwpf;
    uint8_t* wpp8 = (uint8_t*)pwpp8;
    uint8_t* wp8  = (uint8_t*)pwp8;
    float*   g1   = (float*)pg1;
    float*   c2s  = (float*)pc2s;
    float*   b2   = (float*)pb2;
    float*   tmp  = (float*)ptmp;
    __nv_bfloat16* Wq_b  = wb;
    __nv_bfloat16* Wk_b  = wb + (size_t)Dq * Hq;
    __nv_bfloat16* Wv_b  = wb + (size_t)2 * Dq * Hq;
    __nv_bfloat16* WoT_b = wb + (size_t)3 * Dq * Hq;

    cudaFuncSetAttribute(mma_gemm_w2s,   cudaFuncAttributeMaxDynamicSharedMemorySize, SMEM_TOTAL);
    cudaFuncSetAttribute(mma_gemm_f8_yu, cudaFuncAttributeMaxDynamicSharedMemorySize, SMEM_TOTAL);
    cudaFuncSetAttribute(mma_gemm_f8<1>, cudaFuncAttributeMaxDynamicSharedMemorySize, SMEM_TOTAL);
    cudaFuncSetAttribute(mma_gemm_f8<2>, cudaFuncAttributeMaxDynamicSharedMemorySize, SMEM_TOTAL);

    // log2(e) / sqrt(512): exp folded into exp2 in the scores epilogue
    const float alpha2 = 0.06376237712562488f;
    dim3 blk(256);

    // 0. prep (3 launches)
    gemv2_k<<<dim3(512, 2), 128>>>(Wk, bqp, Wo, bvp, bop, g1, b2, wpf);
    cvt_x8_c2_k<<<ROWS / 2, blk>>>(X, g1, x8, c2s, rs);
    wprep_k<<<dim3(16, 16, 4), blk>>>(Wq, Wk, Wv, Wo, wb);

    // 1. split-K weight products (f32 atomic accumulate), then convert x16 -> fp8
    mma_gemm_w2s<<<dim3(4, 4, 8), blk, SMEM_TOTAL>>>(Wk_b, Wq_b, WoT_b, Wv_b, wpf);
    cvt_wp_k<<<dim3(256, 2), blk>>>(wpf, wpp8, wp8);

    // 2. batched y + u
    mma_gemm_f8_yu<<<dim3(4, 128, 2), blk, SMEM_TOTAL>>>(x8, wpp8, wp8, y8, u8T);

    // 3. e8 = fp8(8*exp2(y8 @ x8^T * log2e/sqrt(H) + c2s[col])); rs += row sums
    mma_gemm_f8<1><<<dim3(Nq / 128, Nq / 128, Bq), blk, SMEM_TOTAL>>>(
        y8, x8, e8, rs, c2s, nullptr, nullptr,
        Dq, Dq, Dq, Nq,
        (long long)Nq * Dq, (long long)Nq * Dq, (long long)Nq * Nq, alpha2);

    // 4. tmp = (e8 @ u8T)/rs + bias2[col] + X   [final pre-LN, fp32]
    mma_gemm_f8<2><<<dim3(Dq / 128, Nq / 128, Bq), blk, SMEM_TOTAL>>>(
        e8, u8T, tmp, rs, nullptr, b2, X,
        Nq, Nq, ROWS, Dq,
        (long long)Nq * Nq, (long long)Nq, (long long)Nq * Dq, 1.f);

    // 5. LayerNorm
    ln_k<<<ROWS, 128>>>(tmp, ga, be, out);
}